// round 4
// baseline (speedup 1.0000x reference)
#include <cuda_runtime.h>
#include <math.h>
#include <stdint.h>
#include <stddef.h>

#define NT    768
#define NH    12
#define DIM   384
#define PD    128
#define FEAT  2112
#define NPROJ 1152
#define TI    3
#define NTILE 24            // 768/32 j-tiles

#define SCALAR_SCALE 0.14433756729740643f
#define POINT_SCALE  0.13608276348795434f
#define PAIR_SCALE   0.57735026918962584f

// ------------- device scratch -------------
__device__ __align__(16) float g_wall [DIM * NPROJ];
__device__ __align__(16) float g_proj [NT * NPROJ];
__device__ __align__(16) float g_qs   [NH * NT * 16];
__device__ __align__(16) float g_ks   [NH * NT * 16];
__device__ __align__(16) float g_vs   [NH * NT * 16];
__device__ __align__(16) float g_qpg  [NH * NT * 12];
__device__ __align__(16) float g_kpg  [NH * NT * 12];
__device__ __align__(16) float g_vpg  [NH * NT * 24];
__device__ __align__(16) float g_bias [(size_t)NH * NT * NT];
__device__ __align__(16) float g_feats[(size_t)NT * FEAT];

// ------------- pack weights -------------
__global__ __launch_bounds__(256) void pack_w(
    const float* __restrict__ Wq,  const float* __restrict__ Wk,
    const float* __restrict__ Wv,  const float* __restrict__ Wpq,
    const float* __restrict__ Wpk, const float* __restrict__ Wpv)
{
    int e = blockIdx.x * 256 + threadIdx.x;
    if (e >= DIM * NPROJ) return;
    int r = e / NPROJ, c = e % NPROJ;
    float v;
    if      (c < 192) v = Wq [r*192 + c];
    else if (c < 384) v = Wk [r*192 + (c-192)];
    else if (c < 576) v = Wv [r*192 + (c-384)];
    else if (c < 720) v = Wpq[r*144 + (c-576)];
    else if (c < 864) v = Wpk[r*144 + (c-720)];
    else              v = Wpv[r*288 + (c-864)];
    g_wall[e] = v;
}

// ------------- tiled SGEMM (exact-divisible shapes) -------------
__global__ __launch_bounds__(256) void sgemm64(
    const float* __restrict__ A, const float* __restrict__ B,
    float* __restrict__ C, const float* __restrict__ bias,
    int M, int N, int K)
{
    __shared__ float As[16][65];
    __shared__ float Bs[16][64];
    const int tid = threadIdx.x;
    const int tx = tid % 16, ty = tid / 16;
    const int row0 = blockIdx.y * 64, col0 = blockIdx.x * 64;

    float acc[4][4];
#pragma unroll
    for (int m = 0; m < 4; m++)
#pragma unroll
        for (int n = 0; n < 4; n++) acc[m][n] = 0.f;

    for (int k0 = 0; k0 < K; k0 += 16) {
        {
            int r = tid / 4, c4 = tid % 4;
            float4 v = *reinterpret_cast<const float4*>(&A[(size_t)(row0+r)*K + k0 + c4*4]);
            As[c4*4+0][r] = v.x; As[c4*4+1][r] = v.y;
            As[c4*4+2][r] = v.z; As[c4*4+3][r] = v.w;
        }
        {
            int r = tid / 16, c4 = tid % 16;
            *reinterpret_cast<float4*>(&Bs[r][c4*4]) =
                *reinterpret_cast<const float4*>(&B[(size_t)(k0+r)*N + col0 + c4*4]);
        }
        __syncthreads();
#pragma unroll
        for (int kk = 0; kk < 16; kk++) {
            float a[4], b[4];
#pragma unroll
            for (int m = 0; m < 4; m++) a[m] = As[kk][ty*4 + m];
#pragma unroll
            for (int n = 0; n < 4; n++) b[n] = Bs[kk][tx*4 + n];
#pragma unroll
            for (int m = 0; m < 4; m++)
#pragma unroll
                for (int n = 0; n < 4; n++) acc[m][n] += a[m]*b[n];
        }
        __syncthreads();
    }
#pragma unroll
    for (int m = 0; m < 4; m++) {
        int r = row0 + ty*4 + m;
#pragma unroll
        for (int n = 0; n < 4; n++) {
            int c = col0 + tx*4 + n;
            float v = acc[m][n];
            if (bias) v += bias[c];
            C[(size_t)r*N + c] = v;
        }
    }
}

// ------------- relayout + rotate points to global frame -------------
__global__ __launch_bounds__(128) void relayout(
    const float* __restrict__ rot, const float* __restrict__ trans)
{
    const int i = blockIdx.x, t = threadIdx.x;
    __shared__ float R[9], tv[3];
    if (t < 9) R[t]  = rot[i*9 + t];
    if (t < 3) tv[t] = trans[i*3 + t];
    __syncthreads();
    const float* pr = g_proj + (size_t)i * NPROJ;
    for (int e = t; e < NH*16; e += 128) {
        int h = e/16, d = e%16;
        g_qs[((size_t)h*NT+i)*16+d] = pr[      h*16+d];
        g_ks[((size_t)h*NT+i)*16+d] = pr[192 + h*16+d];
        g_vs[((size_t)h*NT+i)*16+d] = pr[384 + h*16+d];
    }
    for (int e = t; e < NH*4; e += 128) {
        int h = e/4, p = e%4;
        const float* s = pr + 576 + h*12 + p*3;
        float x=s[0], y=s[1], z=s[2];
        float* o = g_qpg + ((size_t)h*NT+i)*12 + p*3;
        o[0]=R[0]*x+R[1]*y+R[2]*z+tv[0];
        o[1]=R[3]*x+R[4]*y+R[5]*z+tv[1];
        o[2]=R[6]*x+R[7]*y+R[8]*z+tv[2];
        s = pr + 720 + h*12 + p*3; x=s[0]; y=s[1]; z=s[2];
        o = g_kpg + ((size_t)h*NT+i)*12 + p*3;
        o[0]=R[0]*x+R[1]*y+R[2]*z+tv[0];
        o[1]=R[3]*x+R[4]*y+R[5]*z+tv[1];
        o[2]=R[6]*x+R[7]*y+R[8]*z+tv[2];
    }
    for (int e = t; e < NH*8; e += 128) {
        int h = e/8, p = e%8;
        const float* s = pr + 864 + h*24 + p*3;
        float x=s[0], y=s[1], z=s[2];
        float* o = g_vpg + ((size_t)h*NT+i)*24 + p*3;
        o[0]=R[0]*x+R[1]*y+R[2]*z+tv[0];
        o[1]=R[3]*x+R[4]*y+R[5]*z+tv[1];
        o[2]=R[6]*x+R[7]*y+R[8]*z+tv[2];
    }
}

// ------------- pair bias as register-blocked GEMM -------------
// C[ij, h] = (pair[ij, :] @ Wpb[:, h] + bpb[h]) * PAIR_SCALE
// CTA: 64 ij-rows, 256 threads = 64 rows x 4 head-groups (3 heads each).
__global__ __launch_bounds__(256) void bias_k(
    const float* __restrict__ pair, const float* __restrict__ Wpb,
    const float* __restrict__ bpb)
{
    __shared__ float tile[64][132];
    __shared__ float wT[12][128];
    __shared__ float bb[12];
    const int tid = threadIdx.x;
    const size_t row0 = (size_t)blockIdx.x * 64;

    for (int e = tid; e < 12*128; e += 256) {
        int h = e >> 7, d = e & 127;
        wT[h][d] = Wpb[d*12 + h];
    }
    if (tid < 12) bb[tid] = bpb[tid];

    // stage 64x128 tile, coalesced float4
    for (int e = tid; e < 64*32; e += 256) {
        int r = e >> 5, c = e & 31;
        float4 v = *reinterpret_cast<const float4*>(pair + (row0 + r)*PD + c*4);
        *reinterpret_cast<float4*>(&tile[r][c*4]) = v;
    }
    __syncthreads();

    const int r = tid >> 2;
    const int g = tid & 3;
    float a0 = 0.f, a1 = 0.f, a2 = 0.f;
    const float* w0 = wT[3*g + 0];
    const float* w1 = wT[3*g + 1];
    const float* w2 = wT[3*g + 2];
#pragma unroll
    for (int c = 0; c < 32; c++) {
        float4 p = *reinterpret_cast<const float4*>(&tile[r][c*4]);
        float4 v0 = *reinterpret_cast<const float4*>(&w0[c*4]);
        float4 v1 = *reinterpret_cast<const float4*>(&w1[c*4]);
        float4 v2 = *reinterpret_cast<const float4*>(&w2[c*4]);
        a0 += p.x*v0.x + p.y*v0.y + p.z*v0.z + p.w*v0.w;
        a1 += p.x*v1.x + p.y*v1.y + p.z*v1.z + p.w*v1.w;
        a2 += p.x*v2.x + p.y*v2.y + p.z*v2.z + p.w*v2.w;
    }
    const size_t NTNT = (size_t)NT*NT;
    g_bias[(size_t)(3*g+0)*NTNT + row0 + r] = (a0 + bb[3*g+0]) * PAIR_SCALE;
    g_bias[(size_t)(3*g+1)*NTNT + row0 + r] = (a1 + bb[3*g+1]) * PAIR_SCALE;
    g_bias[(size_t)(3*g+2)*NTNT + row0 + r] = (a2 + bb[3*g+2]) * PAIR_SCALE;
}

// ------------- fused attention: 3 queries per CTA, 12 warps = 12 heads -----
// dynamic smem layout (floats):
#define PRS_OFF 0                    // [3][32][132]
#define ACC_OFF 12672                // [3][12][168]
#define PPS_OFF 18720                // [3][12][32]
#define QSS_OFF 19872                // [3][12][16]
#define QPS_OFF 20448                // [3][12][12]
#define MST_OFF 20880                // [3][12]
#define LST_OFF 20916                // [3][12]
#define FAC_OFF 20952                // [3][12]
#define RS_OFF  20988                // [3][9]
#define TV_OFF  21015                // [3][3]
#define SMEM_FLOATS 21024

__global__ __launch_bounds__(384, 2) void attn_k(
    const float* __restrict__ pair, const float* __restrict__ rot,
    const float* __restrict__ trans, const float* __restrict__ pwts)
{
    extern __shared__ float sm[];
    float* prs  = sm + PRS_OFF;
    float* accs = sm + ACC_OFF;
    float* pps  = sm + PPS_OFF;
    float* qss  = sm + QSS_OFF;
    float* qps  = sm + QPS_OFF;
    float* mst  = sm + MST_OFF;
    float* lst  = sm + LST_OFF;
    float* facs = sm + FAC_OFF;
    float* Rs   = sm + RS_OFF;
    float* tvs  = sm + TV_OFF;

    const int i0 = blockIdx.x * TI;
    const int t  = threadIdx.x;
    const int h  = t >> 5, lane = t & 31;

    for (int e = t; e < TI*NH*168; e += 384) accs[e] = 0.f;
    for (int e = t; e < TI*NH*16;  e += 384) {
        int q = e / (NH*16), rem = e % (NH*16);
        qss[e] = g_qs[((size_t)(rem/16)*NT + i0 + q)*16 + rem%16];
    }
    for (int e = t; e < TI*NH*12;  e += 384) {
        int q = e / (NH*12), rem = e % (NH*12);
        qps[e] = g_qpg[((size_t)(rem/12)*NT + i0 + q)*12 + rem%12];
    }
    if (t < TI*NH) { mst[t] = -1e30f; lst[t] = 0.f; }
    if (t < TI*9)  Rs[t]  = rot[(i0 + t/9)*9 + t%9];
    if (t < TI*3)  tvs[t] = trans[(i0 + t/3)*3 + t%3];
    __syncthreads();

    float wv = pwts[h];
    float pwh = (wv > 20.f) ? wv : log1pf(expf(wv));
    const float pscale = -0.5f * POINT_SCALE * pwh;

    for (int jt = 0; jt < NTILE; jt++) {
        const int j0 = jt * 32;
        // ---- stage pair tiles for 3 queries (coalesced float4) ----
        for (int e = t; e < TI*32*32; e += 384) {
            int q = e >> 10, rem = e & 1023;
            int r = rem >> 5, c = rem & 31;
            float4 v = *reinterpret_cast<const float4*>(
                pair + ((size_t)(i0+q)*NT + j0 + r)*PD + c*4);
            *reinterpret_cast<float4*>(&prs[(q*32 + r)*132 + c*4]) = v;
        }
        // ---- logits + online softmax (warp h, lane = j) ----
        {
            const int j = j0 + lane;
            const float4* kr = reinterpret_cast<const float4*>(g_ks  + ((size_t)h*NT + j)*16);
            const float4* kp = reinterpret_cast<const float4*>(g_kpg + ((size_t)h*NT + j)*12);
            float4 k0 = kr[0], k1 = kr[1], k2 = kr[2], k3 = kr[3];
            float4 p0 = kp[0], p1 = kp[1], p2 = kp[2];
#pragma unroll
            for (int q = 0; q < TI; q++) {
                const float4* qsv = reinterpret_cast<const float4*>(qss + (q*NH + h)*16);
                const float4* qpv = reinterpret_cast<const float4*>(qps + (q*NH + h)*12);
                float4 a0 = qsv[0], a1 = qsv[1], a2 = qsv[2], a3 = qsv[3];
                float s = a0.x*k0.x + a0.y*k0.y + a0.z*k0.z + a0.w*k0.w
                        + a1.x*k1.x + a1.y*k1.y + a1.z*k1.z + a1.w*k1.w
                        + a2.x*k2.x + a2.y*k2.y + a2.z*k2.z + a2.w*k2.w
                        + a3.x*k3.x + a3.y*k3.y + a3.z*k3.z + a3.w*k3.w;
                s *= SCALAR_SCALE;
                float4 b0 = qpv[0], b1 = qpv[1], b2 = qpv[2];
                float dx, dist = 0.f;
                dx = b0.x-p0.x; dist += dx*dx; dx = b0.y-p0.y; dist += dx*dx;
                dx = b0.z-p0.z; dist += dx*dx; dx = b0.w-p0.w; dist += dx*dx;
                dx = b1.x-p1.x; dist += dx*dx; dx = b1.y-p1.y; dist += dx*dx;
                dx = b1.z-p1.z; dist += dx*dx; dx = b1.w-p1.w; dist += dx*dx;
                dx = b2.x-p2.x; dist += dx*dx; dx = b2.y-p2.y; dist += dx*dx;
                dx = b2.z-p2.z; dist += dx*dx; dx = b2.w-p2.w; dist += dx*dx;
                s += pscale * dist;
                s += g_bias[(size_t)h*NT*NT + (size_t)(i0+q)*NT + j];

                float mx = s;
                for (int o = 16; o; o >>= 1) mx = fmaxf(mx, __shfl_xor_sync(~0u, mx, o));
                float m_old = mst[q*NH + h];
                float m_new = fmaxf(m_old, mx);
                float p = __expf(s - m_new);
                pps[(q*NH + h)*32 + lane] = p;
                float ps = p;
                for (int o = 16; o; o >>= 1) ps += __shfl_xor_sync(~0u, ps, o);
                if (lane == 0) {
                    float f = __expf(m_old - m_new);
                    facs[q*NH + h] = f;
                    lst[q*NH + h] = lst[q*NH + h]*f + ps;
                    mst[q*NH + h] = m_new;
                }
                __syncwarp();
            }
        }
        __syncthreads();
        // ---- rescale + accumulate: 1512 float4 units over 384 threads ----
        for (int u = t; u < TI*NH*42; u += 384) {
            int q = u / (NH*42);
            int o = u % (NH*42);
            int hh = o / 42;
            int c  = o % 42;
            float f = facs[q*NH + hh];
            float* ap = accs + ((q*NH + hh)*168) + c*4;
            float4 a = *reinterpret_cast<float4*>(ap);
            a.x *= f; a.y *= f; a.z *= f; a.w *= f;
            const float* pph = pps + (q*NH + hh)*32;
            if (c < 4) {
                const float* src = g_vs + ((size_t)hh*NT + j0)*16 + c*4;
#pragma unroll 8
                for (int j = 0; j < 32; j++) {
                    float p = pph[j];
                    float4 v = *reinterpret_cast<const float4*>(src + (size_t)j*16);
                    a.x += p*v.x; a.y += p*v.y; a.z += p*v.z; a.w += p*v.w;
                }
            } else if (c < 10) {
                const float* src = g_vpg + ((size_t)hh*NT + j0)*24 + (c-4)*4;
#pragma unroll 8
                for (int j = 0; j < 32; j++) {
                    float p = pph[j];
                    float4 v = *reinterpret_cast<const float4*>(src + (size_t)j*24);
                    a.x += p*v.x; a.y += p*v.y; a.z += p*v.z; a.w += p*v.w;
                }
            } else {
                const float* src = prs + (q*32)*132 + (c-10)*4;
#pragma unroll 8
                for (int j = 0; j < 32; j++) {
                    float p = pph[j];
                    float4 v = *reinterpret_cast<const float4*>(src + j*132);
                    a.x += p*v.x; a.y += p*v.y; a.z += p*v.z; a.w += p*v.w;
                }
            }
            *reinterpret_cast<float4*>(ap) = a;
        }
        __syncthreads();
    }

    // ---- finalize ----
    for (int e = t; e < TI*NH*16; e += 384) {
        int q = e / (NH*16), rem = e % (NH*16);
        int hh = rem/16, d = rem%16;
        g_feats[(size_t)(i0+q)*FEAT + hh*16 + d] =
            accs[(q*NH+hh)*168 + d] / lst[q*NH+hh];
    }
    for (int e = t; e < TI*NH*8; e += 384) {
        int q = e / (NH*8), rem = e % (NH*8);
        int hh = rem/8, p = rem%8;
        float inv = 1.f / lst[q*NH+hh];
        const float* R = Rs + q*9;
        const float* tv = tvs + q*3;
        const float* ac = accs + (q*NH+hh)*168 + 16 + p*3;
        float gx = ac[0]*inv - tv[0];
        float gy = ac[1]*inv - tv[1];
        float gz = ac[2]*inv - tv[2];
        float lx = R[0]*gx + R[3]*gy + R[6]*gz;
        float ly = R[1]*gx + R[4]*gy + R[7]*gz;
        float lz = R[2]*gx + R[5]*gy + R[8]*gz;
        float* fo = g_feats + (size_t)(i0+q)*FEAT;
        fo[192 + hh*24 + p*3 + 0] = lx;
        fo[192 + hh*24 + p*3 + 1] = ly;
        fo[192 + hh*24 + p*3 + 2] = lz;
        fo[480 + hh*8 + p] = sqrtf(lx*lx + ly*ly + lz*lz + 1e-8f);
    }
    for (int e = t; e < TI*NH*PD; e += 384) {
        int q = e / (NH*PD), rem = e % (NH*PD);
        int hh = rem/PD, d = rem%PD;
        g_feats[(size_t)(i0+q)*FEAT + 576 + hh*PD + d] =
            accs[(q*NH+hh)*168 + 40 + d] / lst[q*NH+hh];
    }
}

// ------------- launch -------------
extern "C" void kernel_launch(void* const* d_in, const int* in_sizes, int n_in,
                              void* d_out, int out_size)
{
    (void)in_sizes; (void)n_in; (void)out_size;
    const float* x     = (const float*)d_in[0];
    const float* pair  = (const float*)d_in[1];
    const float* rot   = (const float*)d_in[2];
    const float* trans = (const float*)d_in[3];
    const float* Wq    = (const float*)d_in[4];
    const float* Wk    = (const float*)d_in[5];
    const float* Wv    = (const float*)d_in[6];
    const float* Wpq   = (const float*)d_in[7];
    const float* Wpk   = (const float*)d_in[8];
    const float* Wpv   = (const float*)d_in[9];
    const float* Wpb   = (const float*)d_in[10];
    const float* bpb   = (const float*)d_in[11];
    const float* pwts  = (const float*)d_in[12];
    const float* Wout  = (const float*)d_in[13];
    const float* bout  = (const float*)d_in[14];
    float* out = (float*)d_out;

    static int smem_set = 0;
    if (!smem_set) {
        cudaFuncSetAttribute(attn_k, cudaFuncAttributeMaxDynamicSharedMemorySize,
                             SMEM_FLOATS * 4);
        smem_set = 1;
    }

    void *p_wall, *p_proj, *p_feats;
    cudaGetSymbolAddress(&p_wall,  g_wall);
    cudaGetSymbolAddress(&p_proj,  g_proj);
    cudaGetSymbolAddress(&p_feats, g_feats);

    pack_w<<<(DIM*NPROJ + 255)/256, 256>>>(Wq, Wk, Wv, Wpq, Wpk, Wpv);
    {
        dim3 g(NPROJ/64, NT/64);
        sgemm64<<<g, 256>>>(x, (const float*)p_wall, (float*)p_proj, nullptr,
                            NT, NPROJ, DIM);
    }
    relayout<<<NT, 128>>>(rot, trans);
    bias_k<<<(NT*NT)/64, 256>>>(pair, Wpb, bpb);
    attn_k<<<NT/TI, 384, SMEM_FLOATS*4>>>(pair, rot, trans, pwts);
    {
        dim3 g(DIM/64, NT/64);
        sgemm64<<<g, 256>>>((const float*)p_feats, Wout, out, bout,
                            NT, DIM, FEAT);
    }
}

// round 5
// speedup vs baseline: 1.3955x; 1.3955x over previous
#include <cuda_runtime.h>
#include <math.h>
#include <stdint.h>
#include <stddef.h>

#define NT    768
#define NH    12
#define DIM   384
#define PD    128
#define FEAT  2112
#define NPROJ 1152
#define TI    3
#define NTILE 24

#define SCALAR_SCALE 0.14433756729740643f
#define POINT_SCALE  0.13608276348795434f
#define PAIR_SCALE   0.57735026918962584f

// ------------- device scratch -------------
__device__ __align__(16) float g_wall [DIM * NPROJ];
__device__ __align__(16) float g_proj [NT * NPROJ];
__device__ __align__(16) float g_qs   [NH * NT * 16];
__device__ __align__(16) float g_ks   [NH * NT * 16];
__device__ __align__(16) float g_vs   [NH * NT * 16];
__device__ __align__(16) float g_qpg  [NH * NT * 12];
__device__ __align__(16) float g_kpg  [NH * NT * 12];
__device__ __align__(16) float g_vpg  [NH * NT * 24];
__device__ __align__(16) float g_bias [(size_t)NH * NT * NT];
__device__ __align__(16) float g_feats[(size_t)NT * FEAT];
__device__ __align__(16) float g_part [3 * NT * DIM];

// ------------- pack weights -------------
__global__ __launch_bounds__(256) void pack_w(
    const float* __restrict__ Wq,  const float* __restrict__ Wk,
    const float* __restrict__ Wv,  const float* __restrict__ Wpq,
    const float* __restrict__ Wpk, const float* __restrict__ Wpv)
{
    int e = blockIdx.x * 256 + threadIdx.x;
    if (e >= DIM * NPROJ) return;
    int r = e / NPROJ, c = e % NPROJ;
    float v;
    if      (c < 192) v = Wq [r*192 + c];
    else if (c < 384) v = Wk [r*192 + (c-192)];
    else if (c < 576) v = Wv [r*192 + (c-384)];
    else if (c < 720) v = Wpq[r*144 + (c-576)];
    else if (c < 864) v = Wpk[r*144 + (c-720)];
    else              v = Wpv[r*288 + (c-864)];
    g_wall[e] = v;
}

// ------------- split-K SGEMM: 64x64 tile, TM=8 TN=4, 128 threads ----------
// Writes raw partial (no bias) to C + blockIdx.z*M*N. K must divide gridDim.z
// and each chunk must divide 16.
__global__ __launch_bounds__(128) void sgemm_sk(
    const float* __restrict__ A, const float* __restrict__ B,
    float* __restrict__ C, int M, int N, int K)
{
    __shared__ float As[16][64];
    __shared__ float Bs[16][68];
    const int tid = threadIdx.x;
    const int tx = tid & 15, ty = tid >> 4;          // ty 0..7
    const int row0 = blockIdx.y * 64, col0 = blockIdx.x * 64;
    const int kchunk = K / gridDim.z;
    const int kbeg = blockIdx.z * kchunk;

    float acc[8][4];
#pragma unroll
    for (int m = 0; m < 8; m++)
#pragma unroll
        for (int n = 0; n < 4; n++) acc[m][n] = 0.f;

    for (int k0 = kbeg; k0 < kbeg + kchunk; k0 += 16) {
        for (int e = tid; e < 256; e += 128) {       // A: 64x16
            int r = e >> 2, c4 = e & 3;
            float4 v = *reinterpret_cast<const float4*>(
                &A[(size_t)(row0+r)*K + k0 + c4*4]);
            As[c4*4+0][r] = v.x; As[c4*4+1][r] = v.y;
            As[c4*4+2][r] = v.z; As[c4*4+3][r] = v.w;
        }
        for (int e = tid; e < 256; e += 128) {       // B: 16x64
            int r = e >> 4, c4 = e & 15;
            *reinterpret_cast<float4*>(&Bs[r][c4*4]) =
                *reinterpret_cast<const float4*>(
                    &B[(size_t)(k0+r)*N + col0 + c4*4]);
        }
        __syncthreads();
#pragma unroll
        for (int kk = 0; kk < 16; kk++) {
            float a[8];
#pragma unroll
            for (int m = 0; m < 8; m++) a[m] = As[kk][ty*8 + m];
            float4 b = *reinterpret_cast<const float4*>(&Bs[kk][tx*4]);
#pragma unroll
            for (int m = 0; m < 8; m++) {
                acc[m][0] += a[m]*b.x; acc[m][1] += a[m]*b.y;
                acc[m][2] += a[m]*b.z; acc[m][3] += a[m]*b.w;
            }
        }
        __syncthreads();
    }
    float* Cz = C + (size_t)blockIdx.z * M * N;
#pragma unroll
    for (int m = 0; m < 8; m++) {
        int r = row0 + ty*8 + m;
        float4 v = make_float4(acc[m][0], acc[m][1], acc[m][2], acc[m][3]);
        *reinterpret_cast<float4*>(&Cz[(size_t)r*N + col0 + tx*4]) = v;
    }
}

// ------------- split-K reduce (+ output bias) -------------
__global__ __launch_bounds__(256) void reduce_k(
    float* __restrict__ out, const float* __restrict__ bout)
{
    int e = blockIdx.x * 256 + threadIdx.x;
    if (e >= NT * DIM) return;
    float s = g_part[e] + g_part[NT*DIM + e] + g_part[2*NT*DIM + e];
    out[e] = s + bout[e % DIM];
}

// ------------- relayout + rotate points to global frame -------------
__global__ __launch_bounds__(128) void relayout(
    const float* __restrict__ rot, const float* __restrict__ trans)
{
    const int i = blockIdx.x, t = threadIdx.x;
    __shared__ float R[9], tv[3];
    if (t < 9) R[t]  = rot[i*9 + t];
    if (t < 3) tv[t] = trans[i*3 + t];
    __syncthreads();
    const float* pr = g_proj + (size_t)i * NPROJ;
    for (int e = t; e < NH*16; e += 128) {
        int h = e/16, d = e%16;
        g_qs[((size_t)h*NT+i)*16+d] = pr[      h*16+d];
        g_ks[((size_t)h*NT+i)*16+d] = pr[192 + h*16+d];
        g_vs[((size_t)h*NT+i)*16+d] = pr[384 + h*16+d];
    }
    for (int e = t; e < NH*4; e += 128) {
        int h = e/4, p = e%4;
        const float* s = pr + 576 + h*12 + p*3;
        float x=s[0], y=s[1], z=s[2];
        float* o = g_qpg + ((size_t)h*NT+i)*12 + p*3;
        o[0]=R[0]*x+R[1]*y+R[2]*z+tv[0];
        o[1]=R[3]*x+R[4]*y+R[5]*z+tv[1];
        o[2]=R[6]*x+R[7]*y+R[8]*z+tv[2];
        s = pr + 720 + h*12 + p*3; x=s[0]; y=s[1]; z=s[2];
        o = g_kpg + ((size_t)h*NT+i)*12 + p*3;
        o[0]=R[0]*x+R[1]*y+R[2]*z+tv[0];
        o[1]=R[3]*x+R[4]*y+R[5]*z+tv[1];
        o[2]=R[6]*x+R[7]*y+R[8]*z+tv[2];
    }
    for (int e = t; e < NH*8; e += 128) {
        int h = e/8, p = e%8;
        const float* s = pr + 864 + h*24 + p*3;
        float x=s[0], y=s[1], z=s[2];
        float* o = g_vpg + ((size_t)h*NT+i)*24 + p*3;
        o[0]=R[0]*x+R[1]*y+R[2]*z+tv[0];
        o[1]=R[3]*x+R[4]*y+R[5]*z+tv[1];
        o[2]=R[6]*x+R[7]*y+R[8]*z+tv[2];
    }
}

// ------------- pair bias: outer-product GEMM, conflict-free -------------
// Thread owns 1 ij-row (half of K) x 12 head accumulators in registers.
// tile stride 129 (odd) -> 32 lanes reading 32 rows are bank-conflict-free.
// weights: 3x LDS.128 broadcast per k. One shfl_xor(16) combines K-halves.
__global__ __launch_bounds__(128) void bias_k(
    const float* __restrict__ pair, const float* __restrict__ Wpb,
    const float* __restrict__ bpb)
{
    __shared__ float tile[64 * 129];
    __shared__ float wB[128 * 12];
    __shared__ float bb[12];
    const int tid = threadIdx.x;
    const size_t row0 = (size_t)blockIdx.x * 64;

    for (int e = tid; e < 128*12; e += 128) wB[e] = Wpb[e];  // [d][h] row-major
    if (tid < 12) bb[tid] = bpb[tid];
    for (int e = tid; e < 2048; e += 128) {
        int r = e >> 5, c4 = e & 31;
        float4 v = *reinterpret_cast<const float4*>(pair + (row0 + r)*PD + c4*4);
        float* d = &tile[r*129 + c4*4];
        d[0] = v.x; d[1] = v.y; d[2] = v.z; d[3] = v.w;
    }
    __syncthreads();

    const int warp = tid >> 5, lane = tid & 31;
    const int r    = warp*16 + (lane & 15);
    const int half = lane >> 4;
    float a[12];
#pragma unroll
    for (int h = 0; h < 12; h++) a[h] = 0.f;
    const float* trow = &tile[r*129];
#pragma unroll 4
    for (int k = 0; k < 64; k++) {
        int c = half ? (64 + ((k + 16) & 63)) : k;
        float av = trow[c];
        const float4* w4 = reinterpret_cast<const float4*>(&wB[c*12]);
        float4 w0 = w4[0], w1 = w4[1], w2 = w4[2];
        a[0] += av*w0.x; a[1] += av*w0.y; a[2]  += av*w0.z; a[3]  += av*w0.w;
        a[4] += av*w1.x; a[5] += av*w1.y; a[6]  += av*w1.z; a[7]  += av*w1.w;
        a[8] += av*w2.x; a[9] += av*w2.y; a[10] += av*w2.z; a[11] += av*w2.w;
    }
#pragma unroll
    for (int h = 0; h < 12; h++)
        a[h] += __shfl_xor_sync(~0u, a[h], 16);
    if (half == 0) {
        const size_t NTNT = (size_t)NT * NT;
#pragma unroll
        for (int h = 0; h < 12; h++)
            g_bias[(size_t)h*NTNT + row0 + r] = (a[h] + bb[h]) * PAIR_SCALE;
    }
}

// ------------- fused attention: 3 queries/CTA, 12 warps = 12 heads -----
#define PRS_OFF 0
#define ACC_OFF 12672
#define PPS_OFF 18720
#define QSS_OFF 19872
#define QPS_OFF 20448
#define MST_OFF 20880
#define LST_OFF 20916
#define FAC_OFF 20952
#define RS_OFF  20988
#define TV_OFF  21015
#define SMEM_FLOATS 21024

__global__ __launch_bounds__(384, 2) void attn_k(
    const float* __restrict__ pair, const float* __restrict__ rot,
    const float* __restrict__ trans, const float* __restrict__ pwts)
{
    extern __shared__ float sm[];
    float* prs  = sm + PRS_OFF;
    float* accs = sm + ACC_OFF;
    float* pps  = sm + PPS_OFF;
    float* qss  = sm + QSS_OFF;
    float* qps  = sm + QPS_OFF;
    float* mst  = sm + MST_OFF;
    float* lst  = sm + LST_OFF;
    float* facs = sm + FAC_OFF;
    float* Rs   = sm + RS_OFF;
    float* tvs  = sm + TV_OFF;

    const int i0 = blockIdx.x * TI;
    const int t  = threadIdx.x;
    const int h  = t >> 5, lane = t & 31;

    for (int e = t; e < TI*NH*168; e += 384) accs[e] = 0.f;
    for (int e = t; e < TI*NH*16;  e += 384) {
        int q = e / (NH*16), rem = e % (NH*16);
        qss[e] = g_qs[((size_t)(rem/16)*NT + i0 + q)*16 + rem%16];
    }
    for (int e = t; e < TI*NH*12;  e += 384) {
        int q = e / (NH*12), rem = e % (NH*12);
        qps[e] = g_qpg[((size_t)(rem/12)*NT + i0 + q)*12 + rem%12];
    }
    if (t < TI*NH) { mst[t] = -1e30f; lst[t] = 0.f; }
    if (t < TI*9)  Rs[t]  = rot[(i0 + t/9)*9 + t%9];
    if (t < TI*3)  tvs[t] = trans[(i0 + t/3)*3 + t%3];
    __syncthreads();

    float wv = pwts[h];
    float pwh = (wv > 20.f) ? wv : log1pf(expf(wv));
    const float pscale = -0.5f * POINT_SCALE * pwh;

    for (int jt = 0; jt < NTILE; jt++) {
        const int j0 = jt * 32;
        for (int e = t; e < TI*32*32; e += 384) {
            int q = e >> 10, rem = e & 1023;
            int r = rem >> 5, c = rem & 31;
            float4 v = *reinterpret_cast<const float4*>(
                pair + ((size_t)(i0+q)*NT + j0 + r)*PD + c*4);
            *reinterpret_cast<float4*>(&prs[(q*32 + r)*132 + c*4]) = v;
        }
        {
            const int j = j0 + lane;
            const float4* kr = reinterpret_cast<const float4*>(g_ks  + ((size_t)h*NT + j)*16);
            const float4* kp = reinterpret_cast<const float4*>(g_kpg + ((size_t)h*NT + j)*12);
            float4 k0 = kr[0], k1 = kr[1], k2 = kr[2], k3 = kr[3];
            float4 p0 = kp[0], p1 = kp[1], p2 = kp[2];
#pragma unroll
            for (int q = 0; q < TI; q++) {
                const float4* qsv = reinterpret_cast<const float4*>(qss + (q*NH + h)*16);
                const float4* qpv = reinterpret_cast<const float4*>(qps + (q*NH + h)*12);
                float4 a0 = qsv[0], a1 = qsv[1], a2 = qsv[2], a3 = qsv[3];
                float s = a0.x*k0.x + a0.y*k0.y + a0.z*k0.z + a0.w*k0.w
                        + a1.x*k1.x + a1.y*k1.y + a1.z*k1.z + a1.w*k1.w
                        + a2.x*k2.x + a2.y*k2.y + a2.z*k2.z + a2.w*k2.w
                        + a3.x*k3.x + a3.y*k3.y + a3.z*k3.z + a3.w*k3.w;
                s *= SCALAR_SCALE;
                float4 b0 = qpv[0], b1 = qpv[1], b2 = qpv[2];
                float dx, dist = 0.f;
                dx = b0.x-p0.x; dist += dx*dx; dx = b0.y-p0.y; dist += dx*dx;
                dx = b0.z-p0.z; dist += dx*dx; dx = b0.w-p0.w; dist += dx*dx;
                dx = b1.x-p1.x; dist += dx*dx; dx = b1.y-p1.y; dist += dx*dx;
                dx = b1.z-p1.z; dist += dx*dx; dx = b1.w-p1.w; dist += dx*dx;
                dx = b2.x-p2.x; dist += dx*dx; dx = b2.y-p2.y; dist += dx*dx;
                dx = b2.z-p2.z; dist += dx*dx; dx = b2.w-p2.w; dist += dx*dx;
                s += pscale * dist;
                s += g_bias[(size_t)h*NT*NT + (size_t)(i0+q)*NT + j];

                float mx = s;
                for (int o = 16; o; o >>= 1) mx = fmaxf(mx, __shfl_xor_sync(~0u, mx, o));
                float m_old = mst[q*NH + h];
                float m_new = fmaxf(m_old, mx);
                float p = __expf(s - m_new);
                pps[(q*NH + h)*32 + lane] = p;
                float ps = p;
                for (int o = 16; o; o >>= 1) ps += __shfl_xor_sync(~0u, ps, o);
                if (lane == 0) {
                    float f = __expf(m_old - m_new);
                    facs[q*NH + h] = f;
                    lst[q*NH + h] = lst[q*NH + h]*f + ps;
                    mst[q*NH + h] = m_new;
                }
                __syncwarp();
            }
        }
        __syncthreads();
        for (int u = t; u < TI*NH*42; u += 384) {
            int q = u / (NH*42);
            int o = u % (NH*42);
            int hh = o / 42;
            int c  = o % 42;
            float f = facs[q*NH + hh];
            float* ap = accs + ((q*NH + hh)*168) + c*4;
            float4 a = *reinterpret_cast<float4*>(ap);
            a.x *= f; a.y *= f; a.z *= f; a.w *= f;
            const float* pph = pps + (q*NH + hh)*32;
            if (c < 4) {
                const float* src = g_vs + ((size_t)hh*NT + j0)*16 + c*4;
#pragma unroll 8
                for (int j = 0; j < 32; j++) {
                    float p = pph[j];
                    float4 v = *reinterpret_cast<const float4*>(src + (size_t)j*16);
                    a.x += p*v.x; a.y += p*v.y; a.z += p*v.z; a.w += p*v.w;
                }
            } else if (c < 10) {
                const float* src = g_vpg + ((size_t)hh*NT + j0)*24 + (c-4)*4;
#pragma unroll 8
                for (int j = 0; j < 32; j++) {
                    float p = pph[j];
                    float4 v = *reinterpret_cast<const float4*>(src + (size_t)j*24);
                    a.x += p*v.x; a.y += p*v.y; a.z += p*v.z; a.w += p*v.w;
                }
            } else {
                const float* src = prs + (q*32)*132 + (c-10)*4;
#pragma unroll 8
                for (int j = 0; j < 32; j++) {
                    float p = pph[j];
                    float4 v = *reinterpret_cast<const float4*>(src + j*132);
                    a.x += p*v.x; a.y += p*v.y; a.z += p*v.z; a.w += p*v.w;
                }
            }
            *reinterpret_cast<float4*>(ap) = a;
        }
        __syncthreads();
    }

    for (int e = t; e < TI*NH*16; e += 384) {
        int q = e / (NH*16), rem = e % (NH*16);
        int hh = rem/16, d = rem%16;
        g_feats[(size_t)(i0+q)*FEAT + hh*16 + d] =
            accs[(q*NH+hh)*168 + d] / lst[q*NH+hh];
    }
    for (int e = t; e < TI*NH*8; e += 384) {
        int q = e / (NH*8), rem = e % (NH*8);
        int hh = rem/8, p = rem%8;
        float inv = 1.f / lst[q*NH+hh];
        const float* R = Rs + q*9;
        const float* tv = tvs + q*3;
        const float* ac = accs + (q*NH+hh)*168 + 16 + p*3;
        float gx = ac[0]*inv - tv[0];
        float gy = ac[1]*inv - tv[1];
        float gz = ac[2]*inv - tv[2];
        float lx = R[0]*gx + R[3]*gy + R[6]*gz;
        float ly = R[1]*gx + R[4]*gy + R[7]*gz;
        float lz = R[2]*gx + R[5]*gy + R[8]*gz;
        float* fo = g_feats + (size_t)(i0+q)*FEAT;
        fo[192 + hh*24 + p*3 + 0] = lx;
        fo[192 + hh*24 + p*3 + 1] = ly;
        fo[192 + hh*24 + p*3 + 2] = lz;
        fo[480 + hh*8 + p] = sqrtf(lx*lx + ly*ly + lz*lz + 1e-8f);
    }
    for (int e = t; e < TI*NH*PD; e += 384) {
        int q = e / (NH*PD), rem = e % (NH*PD);
        int hh = rem/PD, d = rem%PD;
        g_feats[(size_t)(i0+q)*FEAT + 576 + hh*PD + d] =
            accs[(q*NH+hh)*168 + 40 + d] / lst[q*NH+hh];
    }
}

// ------------- launch -------------
extern "C" void kernel_launch(void* const* d_in, const int* in_sizes, int n_in,
                              void* d_out, int out_size)
{
    (void)in_sizes; (void)n_in; (void)out_size;
    const float* x     = (const float*)d_in[0];
    const float* pair  = (const float*)d_in[1];
    const float* rot   = (const float*)d_in[2];
    const float* trans = (const float*)d_in[3];
    const float* Wq    = (const float*)d_in[4];
    const float* Wk    = (const float*)d_in[5];
    const float* Wv    = (const float*)d_in[6];
    const float* Wpq   = (const float*)d_in[7];
    const float* Wpk   = (const float*)d_in[8];
    const float* Wpv   = (const float*)d_in[9];
    const float* Wpb   = (const float*)d_in[10];
    const float* bpb   = (const float*)d_in[11];
    const float* pwts  = (const float*)d_in[12];
    const float* Wout  = (const float*)d_in[13];
    const float* bout  = (const float*)d_in[14];
    float* out = (float*)d_out;

    cudaFuncSetAttribute(attn_k, cudaFuncAttributeMaxDynamicSharedMemorySize,
                         SMEM_FLOATS * 4);

    void *p_wall, *p_proj, *p_feats, *p_part;
    cudaGetSymbolAddress(&p_wall,  g_wall);
    cudaGetSymbolAddress(&p_proj,  g_proj);
    cudaGetSymbolAddress(&p_feats, g_feats);
    cudaGetSymbolAddress(&p_part,  g_part);

    pack_w<<<(DIM*NPROJ + 255)/256, 256>>>(Wq, Wk, Wv, Wpq, Wpk, Wpv);
    {
        dim3 g(NPROJ/64, NT/64, 1);   // 18 x 12 = 216 CTAs
        sgemm_sk<<<g, 128>>>(x, (const float*)p_wall, (float*)p_proj,
                             NT, NPROJ, DIM);
    }
    relayout<<<NT, 128>>>(rot, trans);
    bias_k<<<(NT*NT)/64, 128>>>(pair, Wpb, bpb);
    attn_k<<<NT/TI, 384, SMEM_FLOATS*4>>>(pair, rot, trans, pwts);
    {
        dim3 g(DIM/64, NT/64, 3);     // 6 x 12 x 3 = 216 CTAs, split-K
        sgemm_sk<<<g, 128>>>((const float*)p_feats, Wout, (float*)p_part,
                             NT, DIM, FEAT);
    }
    reduce_k<<<(NT*DIM + 255)/256, 256>>>(out, bout);
}

// round 6
// speedup vs baseline: 2.2536x; 1.6149x over previous
#include <cuda_runtime.h>
#include <math.h>
#include <stdint.h>
#include <stddef.h>

#define NT    768
#define NH    12
#define DIM   384
#define PD    128
#define FEAT  2112
#define NPROJ 1152
#define TI    3
#define NTILE 24
#define SPLITK 6

#define SCALAR_SCALE 0.14433756729740643f
#define POINT_SCALE  0.13608276348795434f
#define PAIR_SCALE   0.57735026918962584f

// ------------- device scratch -------------
__device__ __align__(16) float g_wall [DIM * NPROJ];
__device__ __align__(16) float g_proj [NT * NPROJ];
__device__ __align__(16) float g_qs   [NH * NT * 16];
__device__ __align__(16) float g_ks   [NH * NT * 16];
__device__ __align__(16) float g_vs   [NH * NT * 16];
__device__ __align__(16) float g_qpg  [NH * NT * 12];
__device__ __align__(16) float g_kpg  [NH * NT * 12];
__device__ __align__(16) float g_vpg  [NH * NT * 24];
__device__ __align__(16) float g_bias [(size_t)NH * NT * NT];
__device__ __align__(16) float g_feats[(size_t)NT * FEAT];
__device__ __align__(16) float g_part [SPLITK * NT * DIM];

// ------------- pack weights -------------
__global__ __launch_bounds__(256) void pack_w(
    const float* __restrict__ Wq,  const float* __restrict__ Wk,
    const float* __restrict__ Wv,  const float* __restrict__ Wpq,
    const float* __restrict__ Wpk, const float* __restrict__ Wpv)
{
    int e = blockIdx.x * 256 + threadIdx.x;
    if (e >= DIM * NPROJ) return;
    int r = e / NPROJ, c = e % NPROJ;
    float v;
    if      (c < 192) v = Wq [r*192 + c];
    else if (c < 384) v = Wk [r*192 + (c-192)];
    else if (c < 576) v = Wv [r*192 + (c-384)];
    else if (c < 720) v = Wpq[r*144 + (c-576)];
    else if (c < 864) v = Wpk[r*144 + (c-720)];
    else              v = Wpv[r*288 + (c-864)];
    g_wall[e] = v;
}

// ------------- split-K SGEMM: 64x64 tile, TM=8 TN=4, 128 threads ----------
__global__ __launch_bounds__(128) void sgemm_sk(
    const float* __restrict__ A, const float* __restrict__ B,
    float* __restrict__ C, int M, int N, int K)
{
    __shared__ float As[16][64];
    __shared__ float Bs[16][68];
    const int tid = threadIdx.x;
    const int tx = tid & 15, ty = tid >> 4;
    const int row0 = blockIdx.y * 64, col0 = blockIdx.x * 64;
    const int kchunk = K / gridDim.z;
    const int kbeg = blockIdx.z * kchunk;

    float acc[8][4];
#pragma unroll
    for (int m = 0; m < 8; m++)
#pragma unroll
        for (int n = 0; n < 4; n++) acc[m][n] = 0.f;

    for (int k0 = kbeg; k0 < kbeg + kchunk; k0 += 16) {
        for (int e = tid; e < 256; e += 128) {
            int r = e >> 2, c4 = e & 3;
            float4 v = *reinterpret_cast<const float4*>(
                &A[(size_t)(row0+r)*K + k0 + c4*4]);
            As[c4*4+0][r] = v.x; As[c4*4+1][r] = v.y;
            As[c4*4+2][r] = v.z; As[c4*4+3][r] = v.w;
        }
        for (int e = tid; e < 256; e += 128) {
            int r = e >> 4, c4 = e & 15;
            *reinterpret_cast<float4*>(&Bs[r][c4*4]) =
                *reinterpret_cast<const float4*>(
                    &B[(size_t)(k0+r)*N + col0 + c4*4]);
        }
        __syncthreads();
#pragma unroll
        for (int kk = 0; kk < 16; kk++) {
            float a[8];
#pragma unroll
            for (int m = 0; m < 8; m++) a[m] = As[kk][ty*8 + m];
            float4 b = *reinterpret_cast<const float4*>(&Bs[kk][tx*4]);
#pragma unroll
            for (int m = 0; m < 8; m++) {
                acc[m][0] += a[m]*b.x; acc[m][1] += a[m]*b.y;
                acc[m][2] += a[m]*b.z; acc[m][3] += a[m]*b.w;
            }
        }
        __syncthreads();
    }
    float* Cz = C + (size_t)blockIdx.z * M * N;
#pragma unroll
    for (int m = 0; m < 8; m++) {
        int r = row0 + ty*8 + m;
        float4 v = make_float4(acc[m][0], acc[m][1], acc[m][2], acc[m][3]);
        *reinterpret_cast<float4*>(&Cz[(size_t)r*N + col0 + tx*4]) = v;
    }
}

// ------------- split-K reduce (+ output bias) -------------
__global__ __launch_bounds__(256) void reduce_k(
    float* __restrict__ out, const float* __restrict__ bout)
{
    int e = blockIdx.x * 256 + threadIdx.x;
    if (e >= NT * DIM) return;
    float s = 0.f;
#pragma unroll
    for (int z = 0; z < SPLITK; z++) s += g_part[(size_t)z*NT*DIM + e];
    out[e] = s + bout[e % DIM];
}

// ------------- relayout + rotate points to global frame -------------
__global__ __launch_bounds__(128) void relayout(
    const float* __restrict__ rot, const float* __restrict__ trans)
{
    const int i = blockIdx.x, t = threadIdx.x;
    __shared__ float R[9], tv[3];
    if (t < 9) R[t]  = rot[i*9 + t];
    if (t < 3) tv[t] = trans[i*3 + t];
    __syncthreads();
    const float* pr = g_proj + (size_t)i * NPROJ;
    for (int e = t; e < NH*16; e += 128) {
        int h = e/16, d = e%16;
        g_qs[((size_t)h*NT+i)*16+d] = pr[      h*16+d];
        g_ks[((size_t)h*NT+i)*16+d] = pr[192 + h*16+d];
        g_vs[((size_t)h*NT+i)*16+d] = pr[384 + h*16+d];
    }
    for (int e = t; e < NH*4; e += 128) {
        int h = e/4, p = e%4;
        const float* s = pr + 576 + h*12 + p*3;
        float x=s[0], y=s[1], z=s[2];
        float* o = g_qpg + ((size_t)h*NT+i)*12 + p*3;
        o[0]=R[0]*x+R[1]*y+R[2]*z+tv[0];
        o[1]=R[3]*x+R[4]*y+R[5]*z+tv[1];
        o[2]=R[6]*x+R[7]*y+R[8]*z+tv[2];
        s = pr + 720 + h*12 + p*3; x=s[0]; y=s[1]; z=s[2];
        o = g_kpg + ((size_t)h*NT+i)*12 + p*3;
        o[0]=R[0]*x+R[1]*y+R[2]*z+tv[0];
        o[1]=R[3]*x+R[4]*y+R[5]*z+tv[1];
        o[2]=R[6]*x+R[7]*y+R[8]*z+tv[2];
    }
    for (int e = t; e < NH*8; e += 128) {
        int h = e/8, p = e%8;
        const float* s = pr + 864 + h*24 + p*3;
        float x=s[0], y=s[1], z=s[2];
        float* o = g_vpg + ((size_t)h*NT+i)*24 + p*3;
        o[0]=R[0]*x+R[1]*y+R[2]*z+tv[0];
        o[1]=R[3]*x+R[4]*y+R[5]*z+tv[1];
        o[2]=R[6]*x+R[7]*y+R[8]*z+tv[2];
    }
}

// ------------- pair bias v3: warp-uniform K-halves, affine indexing ------
// 256 threads: warps 0-3 handle K[0:64) of rows 0..127, warps 4-7 K[64:128).
// Data LDS conflict-free (stride 129); weight LDS true broadcast.
#define BT_TILE   0                     // 128*129
#define BT_W      16512                 // 128*12
#define BT_BB     18048                 // 12
#define BT_PART   18060                 // 128*12
#define BT_FLOATS 19600

__global__ __launch_bounds__(256) void bias_k(
    const float* __restrict__ pair, const float* __restrict__ Wpb,
    const float* __restrict__ bpb)
{
    extern __shared__ float sb[];
    float* tile = sb + BT_TILE;
    float* wB   = sb + BT_W;
    float* bb   = sb + BT_BB;
    float* part = sb + BT_PART;
    const int tid = threadIdx.x;
    const size_t row0 = (size_t)blockIdx.x * 128;

    for (int e = tid; e < 128*12; e += 256) wB[e] = Wpb[e];
    if (tid < 12) bb[tid] = bpb[tid];
    for (int e = tid; e < 4096; e += 256) {
        int r = e >> 5, c4 = e & 31;
        float4 v = *reinterpret_cast<const float4*>(pair + (row0 + r)*PD + c4*4);
        float* d = &tile[r*129 + c4*4];
        d[0] = v.x; d[1] = v.y; d[2] = v.z; d[3] = v.w;
    }
    __syncthreads();

    const int r    = tid & 127;
    const int half = tid >> 7;          // warp-uniform
    float a[12];
#pragma unroll
    for (int h = 0; h < 12; h++) a[h] = 0.f;
    const float* trow = &tile[r*129 + half*64];
    const float* wrow = &wB[half*64*12];
#pragma unroll 4
    for (int k = 0; k < 64; k++) {
        float av = trow[k];
        const float4* w4 = reinterpret_cast<const float4*>(&wrow[k*12]);
        float4 w0 = w4[0], w1 = w4[1], w2 = w4[2];
        a[0] += av*w0.x; a[1] += av*w0.y; a[2]  += av*w0.z; a[3]  += av*w0.w;
        a[4] += av*w1.x; a[5] += av*w1.y; a[6]  += av*w1.z; a[7]  += av*w1.w;
        a[8] += av*w2.x; a[9] += av*w2.y; a[10] += av*w2.z; a[11] += av*w2.w;
    }
    if (half == 1) {
#pragma unroll
        for (int h = 0; h < 12; h++) part[r*12 + h] = a[h];
    }
    __syncthreads();
    if (half == 0) {
        const size_t NTNT = (size_t)NT * NT;
#pragma unroll
        for (int h = 0; h < 12; h++)
            g_bias[(size_t)h*NTNT + row0 + r] =
                (a[h] + part[r*12 + h] + bb[h]) * PAIR_SCALE;
    }
}

// ------------- fused attention: register accumulators -------------
#define PRS_OFF 0                    // [3][32][132]
#define ACC_OFF 12672                // [3][12][168]
#define PPS_OFF 18720                // [3][12][32]
#define QSS_OFF 19872
#define QPS_OFF 20448
#define MST_OFF 20880
#define LST_OFF 20916
#define FAC_OFF 20952
#define RS_OFF  20988
#define TV_OFF  21015
#define SMEM_FLOATS 21024

__global__ __launch_bounds__(384, 2) void attn_k(
    const float* __restrict__ pair, const float* __restrict__ rot,
    const float* __restrict__ trans, const float* __restrict__ pwts)
{
    extern __shared__ float sm[];
    float* prs  = sm + PRS_OFF;
    float* accs = sm + ACC_OFF;
    float* pps  = sm + PPS_OFF;
    float* qss  = sm + QSS_OFF;
    float* qps  = sm + QPS_OFF;
    float* mst  = sm + MST_OFF;
    float* lst  = sm + LST_OFF;
    float* facs = sm + FAC_OFF;
    float* Rs   = sm + RS_OFF;
    float* tvs  = sm + TV_OFF;

    const int i0 = blockIdx.x * TI;
    const int t  = threadIdx.x;
    const int h  = t >> 5, lane = t & 31;

    // accumulate-phase thread roles
    const int hg = t & 1;               // head sextet
    const int jq = (t >> 1) & 1;        // j half
    const int cc = (t >> 2) & 31;       // float4 column of pair
    const int qq = t >> 7;              // query
    const bool has_sp = (t < 360);
    const int q2  = t / 120;
    const int rm2 = t % 120;
    const int hh2 = rm2 / 10;
    const int c2  = rm2 % 10;
    const float* vbase;
    int vstride;
    if (c2 < 4) { vbase = g_vs  + (size_t)hh2*NT*16 + c2*4;     vstride = 16; }
    else        { vbase = g_vpg + (size_t)hh2*NT*24 + (c2-4)*4; vstride = 24; }

    float4 pacc[6];
#pragma unroll
    for (int m = 0; m < 6; m++) pacc[m] = make_float4(0.f,0.f,0.f,0.f);
    float4 spacc = make_float4(0.f,0.f,0.f,0.f);

    for (int e = t; e < TI*NH*16;  e += 384) {
        int q = e / (NH*16), rem = e % (NH*16);
        qss[e] = g_qs[((size_t)(rem/16)*NT + i0 + q)*16 + rem%16];
    }
    for (int e = t; e < TI*NH*12;  e += 384) {
        int q = e / (NH*12), rem = e % (NH*12);
        qps[e] = g_qpg[((size_t)(rem/12)*NT + i0 + q)*12 + rem%12];
    }
    if (t < TI*NH) { mst[t] = -1e30f; lst[t] = 0.f; }
    if (t < TI*9)  Rs[t]  = rot[(i0 + t/9)*9 + t%9];
    if (t < TI*3)  tvs[t] = trans[(i0 + t/3)*3 + t%3];
    __syncthreads();

    float wv = pwts[h];
    float pwh = (wv > 20.f) ? wv : log1pf(expf(wv));
    const float pscale = -0.5f * POINT_SCALE * pwh;

    for (int jt = 0; jt < NTILE; jt++) {
        const int j0 = jt * 32;
        for (int e = t; e < TI*32*32; e += 384) {
            int q = e >> 10, rem = e & 1023;
            int r = rem >> 5, c = rem & 31;
            float4 v = *reinterpret_cast<const float4*>(
                pair + ((size_t)(i0+q)*NT + j0 + r)*PD + c*4);
            *reinterpret_cast<float4*>(&prs[(q*32 + r)*132 + c*4]) = v;
        }
        {
            const int j = j0 + lane;
            const float4* kr = reinterpret_cast<const float4*>(g_ks  + ((size_t)h*NT + j)*16);
            const float4* kp = reinterpret_cast<const float4*>(g_kpg + ((size_t)h*NT + j)*12);
            float4 k0 = kr[0], k1 = kr[1], k2 = kr[2], k3 = kr[3];
            float4 p0 = kp[0], p1 = kp[1], p2 = kp[2];
#pragma unroll
            for (int q = 0; q < TI; q++) {
                const float4* qsv = reinterpret_cast<const float4*>(qss + (q*NH + h)*16);
                const float4* qpv = reinterpret_cast<const float4*>(qps + (q*NH + h)*12);
                float4 a0 = qsv[0], a1 = qsv[1], a2 = qsv[2], a3 = qsv[3];
                float s = a0.x*k0.x + a0.y*k0.y + a0.z*k0.z + a0.w*k0.w
                        + a1.x*k1.x + a1.y*k1.y + a1.z*k1.z + a1.w*k1.w
                        + a2.x*k2.x + a2.y*k2.y + a2.z*k2.z + a2.w*k2.w
                        + a3.x*k3.x + a3.y*k3.y + a3.z*k3.z + a3.w*k3.w;
                s *= SCALAR_SCALE;
                float4 b0 = qpv[0], b1 = qpv[1], b2 = qpv[2];
                float dx, dist = 0.f;
                dx = b0.x-p0.x; dist += dx*dx; dx = b0.y-p0.y; dist += dx*dx;
                dx = b0.z-p0.z; dist += dx*dx; dx = b0.w-p0.w; dist += dx*dx;
                dx = b1.x-p1.x; dist += dx*dx; dx = b1.y-p1.y; dist += dx*dx;
                dx = b1.z-p1.z; dist += dx*dx; dx = b1.w-p1.w; dist += dx*dx;
                dx = b2.x-p2.x; dist += dx*dx; dx = b2.y-p2.y; dist += dx*dx;
                dx = b2.z-p2.z; dist += dx*dx; dx = b2.w-p2.w; dist += dx*dx;
                s += pscale * dist;
                s += g_bias[(size_t)h*NT*NT + (size_t)(i0+q)*NT + j];

                float mx = s;
                for (int o = 16; o; o >>= 1) mx = fmaxf(mx, __shfl_xor_sync(~0u, mx, o));
                float m_old = mst[q*NH + h];
                float m_new = fmaxf(m_old, mx);
                float p = __expf(s - m_new);
                pps[(q*NH + h)*32 + lane] = p;
                float ps = p;
                for (int o = 16; o; o >>= 1) ps += __shfl_xor_sync(~0u, ps, o);
                if (lane == 0) {
                    float f = __expf(m_old - m_new);
                    facs[q*NH + h] = f;
                    lst[q*NH + h] = lst[q*NH + h]*f + ps;
                    mst[q*NH + h] = m_new;
                }
                __syncwarp();
            }
        }
        __syncthreads();
        // ---- pair accumulate in registers: 1 LDS.128 feeds 24 FMA ----
        {
            const float* fq = facs + qq*NH + hg*6;
            float f0=fq[0], f1=fq[1], f2=fq[2], f3=fq[3], f4=fq[4], f5=fq[5];
            pacc[0].x*=f0; pacc[0].y*=f0; pacc[0].z*=f0; pacc[0].w*=f0;
            pacc[1].x*=f1; pacc[1].y*=f1; pacc[1].z*=f1; pacc[1].w*=f1;
            pacc[2].x*=f2; pacc[2].y*=f2; pacc[2].z*=f2; pacc[2].w*=f2;
            pacc[3].x*=f3; pacc[3].y*=f3; pacc[3].z*=f3; pacc[3].w*=f3;
            pacc[4].x*=f4; pacc[4].y*=f4; pacc[4].z*=f4; pacc[4].w*=f4;
            pacc[5].x*=f5; pacc[5].y*=f5; pacc[5].z*=f5; pacc[5].w*=f5;
            const float* pbase = pps + (qq*NH + hg*6)*32 + jq*16;
            const float* prow  = prs + (qq*32 + jq*16)*132 + cc*4;
#pragma unroll
            for (int jj = 0; jj < 16; jj++) {
                float4 v = *reinterpret_cast<const float4*>(prow + jj*132);
                float p0 = pbase[0*32+jj], p1 = pbase[1*32+jj], p2 = pbase[2*32+jj];
                float p3 = pbase[3*32+jj], p4 = pbase[4*32+jj], p5 = pbase[5*32+jj];
                pacc[0].x += p0*v.x; pacc[0].y += p0*v.y; pacc[0].z += p0*v.z; pacc[0].w += p0*v.w;
                pacc[1].x += p1*v.x; pacc[1].y += p1*v.y; pacc[1].z += p1*v.z; pacc[1].w += p1*v.w;
                pacc[2].x += p2*v.x; pacc[2].y += p2*v.y; pacc[2].z += p2*v.z; pacc[2].w += p2*v.w;
                pacc[3].x += p3*v.x; pacc[3].y += p3*v.y; pacc[3].z += p3*v.z; pacc[3].w += p3*v.w;
                pacc[4].x += p4*v.x; pacc[4].y += p4*v.y; pacc[4].z += p4*v.z; pacc[4].w += p4*v.w;
                pacc[5].x += p5*v.x; pacc[5].y += p5*v.y; pacc[5].z += p5*v.z; pacc[5].w += p5*v.w;
            }
        }
        // ---- scalar + point accumulate in registers ----
        if (has_sp) {
            float f = facs[q2*NH + hh2];
            spacc.x *= f; spacc.y *= f; spacc.z *= f; spacc.w *= f;
            const float* pph = pps + (q2*NH + hh2)*32;
            const float* src = vbase + (size_t)j0*vstride;
#pragma unroll 8
            for (int j = 0; j < 32; j++) {
                float p = pph[j];
                float4 v = *reinterpret_cast<const float4*>(src + (size_t)j*vstride);
                spacc.x += p*v.x; spacc.y += p*v.y; spacc.z += p*v.z; spacc.w += p*v.w;
            }
        }
        __syncthreads();
    }

    // ---- merge register accumulators into smem ----
    {
        int base = (qq*NH + hg*6)*168 + 40 + cc*4;
        if (jq == 0) {
#pragma unroll
            for (int m = 0; m < 6; m++)
                *reinterpret_cast<float4*>(accs + base + m*168) = pacc[m];
        }
        if (has_sp) {
            int off = (c2 < 4) ? c2*4 : 16 + (c2-4)*4;
            *reinterpret_cast<float4*>(accs + (q2*NH + hh2)*168 + off) = spacc;
        }
        __syncthreads();
        if (jq == 1) {
#pragma unroll
            for (int m = 0; m < 6; m++) {
                float4* p = reinterpret_cast<float4*>(accs + base + m*168);
                float4 a = *p;
                a.x += pacc[m].x; a.y += pacc[m].y; a.z += pacc[m].z; a.w += pacc[m].w;
                *p = a;
            }
        }
        __syncthreads();
    }

    // ---- finalize ----
    for (int e = t; e < TI*NH*16; e += 384) {
        int q = e / (NH*16), rem = e % (NH*16);
        int hh = rem/16, d = rem%16;
        g_feats[(size_t)(i0+q)*FEAT + hh*16 + d] =
            accs[(q*NH+hh)*168 + d] / lst[q*NH+hh];
    }
    for (int e = t; e < TI*NH*8; e += 384) {
        int q = e / (NH*8), rem = e % (NH*8);
        int hh = rem/8, p = rem%8;
        float inv = 1.f / lst[q*NH+hh];
        const float* R = Rs + q*9;
        const float* tv = tvs + q*3;
        const float* ac = accs + (q*NH+hh)*168 + 16 + p*3;
        float gx = ac[0]*inv - tv[0];
        float gy = ac[1]*inv - tv[1];
        float gz = ac[2]*inv - tv[2];
        float lx = R[0]*gx + R[3]*gy + R[6]*gz;
        float ly = R[1]*gx + R[4]*gy + R[7]*gz;
        float lz = R[2]*gx + R[5]*gy + R[8]*gz;
        float* fo = g_feats + (size_t)(i0+q)*FEAT;
        fo[192 + hh*24 + p*3 + 0] = lx;
        fo[192 + hh*24 + p*3 + 1] = ly;
        fo[192 + hh*24 + p*3 + 2] = lz;
        fo[480 + hh*8 + p] = sqrtf(lx*lx + ly*ly + lz*lz + 1e-8f);
    }
    for (int e = t; e < TI*NH*PD; e += 384) {
        int q = e / (NH*PD), rem = e % (NH*PD);
        int hh = rem/PD, d = rem%PD;
        g_feats[(size_t)(i0+q)*FEAT + 576 + hh*PD + d] =
            accs[(q*NH+hh)*168 + 40 + d] / lst[q*NH+hh];
    }
}

// ------------- launch -------------
extern "C" void kernel_launch(void* const* d_in, const int* in_sizes, int n_in,
                              void* d_out, int out_size)
{
    (void)in_sizes; (void)n_in; (void)out_size;
    const float* x     = (const float*)d_in[0];
    const float* pair  = (const float*)d_in[1];
    const float* rot   = (const float*)d_in[2];
    const float* trans = (const float*)d_in[3];
    const float* Wq    = (const float*)d_in[4];
    const float* Wk    = (const float*)d_in[5];
    const float* Wv    = (const float*)d_in[6];
    const float* Wpq   = (const float*)d_in[7];
    const float* Wpk   = (const float*)d_in[8];
    const float* Wpv   = (const float*)d_in[9];
    const float* Wpb   = (const float*)d_in[10];
    const float* bpb   = (const float*)d_in[11];
    const float* pwts  = (const float*)d_in[12];
    const float* Wout  = (const float*)d_in[13];
    const float* bout  = (const float*)d_in[14];
    float* out = (float*)d_out;

    cudaFuncSetAttribute(attn_k, cudaFuncAttributeMaxDynamicSharedMemorySize,
                         SMEM_FLOATS * 4);
    cudaFuncSetAttribute(bias_k, cudaFuncAttributeMaxDynamicSharedMemorySize,
                         BT_FLOATS * 4);

    void *p_wall, *p_proj, *p_feats, *p_part;
    cudaGetSymbolAddress(&p_wall,  g_wall);
    cudaGetSymbolAddress(&p_proj,  g_proj);
    cudaGetSymbolAddress(&p_feats, g_feats);
    cudaGetSymbolAddress(&p_part,  g_part);

    pack_w<<<(DIM*NPROJ + 255)/256, 256>>>(Wq, Wk, Wv, Wpq, Wpk, Wpv);
    {
        dim3 g(NPROJ/64, NT/64, 1);
        sgemm_sk<<<g, 128>>>(x, (const float*)p_wall, (float*)p_proj,
                             NT, NPROJ, DIM);
    }
    relayout<<<NT, 128>>>(rot, trans);
    bias_k<<<(NT*NT)/128, 256, BT_FLOATS*4>>>(pair, Wpb, bpb);
    attn_k<<<NT/TI, 384, SMEM_FLOATS*4>>>(pair, rot, trans, pwts);
    {
        dim3 g(DIM/64, NT/64, SPLITK);
        sgemm_sk<<<g, 128>>>((const float*)p_feats, Wout, (float*)p_part,
                             NT, DIM, FEAT);
    }
    reduce_k<<<(NT*DIM + 255)/256, 256>>>(out, bout);
}

// round 7
// speedup vs baseline: 2.5507x; 1.1319x over previous
#include <cuda_runtime.h>
#include <math.h>
#include <stdint.h>
#include <stddef.h>

#define NT    768
#define NH    12
#define DIM   384
#define PD    128
#define FEAT  2112
#define NPROJ 1152
#define TI    3
#define NTILE 24
#define SPLITK 6

#define SCALAR_SCALE 0.14433756729740643f
#define POINT_SCALE  0.13608276348795434f
#define PAIR_SCALE   0.57735026918962584f

// ------------- device scratch -------------
__device__ __align__(16) float g_wall [DIM * NPROJ];
__device__ __align__(16) float g_proj [NT * NPROJ];
__device__ __align__(16) float g_qs   [NH * NT * 16];
__device__ __align__(16) float g_ks   [NH * NT * 16];
__device__ __align__(16) float g_vs   [NH * NT * 16];
__device__ __align__(16) float g_qpg  [NH * NT * 12];
__device__ __align__(16) float g_kpg  [NH * NT * 12];
__device__ __align__(16) float g_vpg  [NH * NT * 24];
__device__ __align__(16) float g_bias [(size_t)NH * NT * NT];
__device__ __align__(16) float g_feats[(size_t)NT * FEAT];
__device__ __align__(16) float g_part [SPLITK * NT * DIM];

// ------------- pack weights -------------
__global__ __launch_bounds__(256) void pack_w(
    const float* __restrict__ Wq,  const float* __restrict__ Wk,
    const float* __restrict__ Wv,  const float* __restrict__ Wpq,
    const float* __restrict__ Wpk, const float* __restrict__ Wpv)
{
    int e = blockIdx.x * 256 + threadIdx.x;
    if (e >= DIM * NPROJ) return;
    int r = e / NPROJ, c = e % NPROJ;
    float v;
    if      (c < 192) v = Wq [r*192 + c];
    else if (c < 384) v = Wk [r*192 + (c-192)];
    else if (c < 576) v = Wv [r*192 + (c-384)];
    else if (c < 720) v = Wpq[r*144 + (c-576)];
    else if (c < 864) v = Wpk[r*144 + (c-720)];
    else              v = Wpv[r*288 + (c-864)];
    g_wall[e] = v;
}

// ------------- split-K SGEMM: 64x64 tile, TM=8 TN=4, 128 threads ----------
__global__ __launch_bounds__(128) void sgemm_sk(
    const float* __restrict__ A, const float* __restrict__ B,
    float* __restrict__ C, int M, int N, int K)
{
    __shared__ float As[16][64];
    __shared__ float Bs[16][68];
    const int tid = threadIdx.x;
    const int tx = tid & 15, ty = tid >> 4;
    const int row0 = blockIdx.y * 64, col0 = blockIdx.x * 64;
    const int kchunk = K / gridDim.z;
    const int kbeg = blockIdx.z * kchunk;

    float acc[8][4];
#pragma unroll
    for (int m = 0; m < 8; m++)
#pragma unroll
        for (int n = 0; n < 4; n++) acc[m][n] = 0.f;

    for (int k0 = kbeg; k0 < kbeg + kchunk; k0 += 16) {
        for (int e = tid; e < 256; e += 128) {
            int r = e >> 2, c4 = e & 3;
            float4 v = *reinterpret_cast<const float4*>(
                &A[(size_t)(row0+r)*K + k0 + c4*4]);
            As[c4*4+0][r] = v.x; As[c4*4+1][r] = v.y;
            As[c4*4+2][r] = v.z; As[c4*4+3][r] = v.w;
        }
        for (int e = tid; e < 256; e += 128) {
            int r = e >> 4, c4 = e & 15;
            *reinterpret_cast<float4*>(&Bs[r][c4*4]) =
                *reinterpret_cast<const float4*>(
                    &B[(size_t)(k0+r)*N + col0 + c4*4]);
        }
        __syncthreads();
#pragma unroll
        for (int kk = 0; kk < 16; kk++) {
            float a[8];
#pragma unroll
            for (int m = 0; m < 8; m++) a[m] = As[kk][ty*8 + m];
            float4 b = *reinterpret_cast<const float4*>(&Bs[kk][tx*4]);
#pragma unroll
            for (int m = 0; m < 8; m++) {
                acc[m][0] += a[m]*b.x; acc[m][1] += a[m]*b.y;
                acc[m][2] += a[m]*b.z; acc[m][3] += a[m]*b.w;
            }
        }
        __syncthreads();
    }
    float* Cz = C + (size_t)blockIdx.z * M * N;
#pragma unroll
    for (int m = 0; m < 8; m++) {
        int r = row0 + ty*8 + m;
        float4 v = make_float4(acc[m][0], acc[m][1], acc[m][2], acc[m][3]);
        *reinterpret_cast<float4*>(&Cz[(size_t)r*N + col0 + tx*4]) = v;
    }
}

// ------------- split-K reduce (+ output bias) -------------
__global__ __launch_bounds__(256) void reduce_k(
    float* __restrict__ out, const float* __restrict__ bout)
{
    int e = blockIdx.x * 256 + threadIdx.x;
    if (e >= NT * DIM) return;
    float s = 0.f;
#pragma unroll
    for (int z = 0; z < SPLITK; z++) s += g_part[(size_t)z*NT*DIM + e];
    out[e] = s + bout[e % DIM];
}

// ------------- relayout + rotate points to global frame -------------
__global__ __launch_bounds__(128) void relayout(
    const float* __restrict__ rot, const float* __restrict__ trans)
{
    const int i = blockIdx.x, t = threadIdx.x;
    __shared__ float R[9], tv[3];
    if (t < 9) R[t]  = rot[i*9 + t];
    if (t < 3) tv[t] = trans[i*3 + t];
    __syncthreads();
    const float* pr = g_proj + (size_t)i * NPROJ;
    for (int e = t; e < NH*16; e += 128) {
        int h = e/16, d = e%16;
        g_qs[((size_t)h*NT+i)*16+d] = pr[      h*16+d];
        g_ks[((size_t)h*NT+i)*16+d] = pr[192 + h*16+d];
        g_vs[((size_t)h*NT+i)*16+d] = pr[384 + h*16+d];
    }
    for (int e = t; e < NH*4; e += 128) {
        int h = e/4, p = e%4;
        const float* s = pr + 576 + h*12 + p*3;
        float x=s[0], y=s[1], z=s[2];
        float* o = g_qpg + ((size_t)h*NT+i)*12 + p*3;
        o[0]=R[0]*x+R[1]*y+R[2]*z+tv[0];
        o[1]=R[3]*x+R[4]*y+R[5]*z+tv[1];
        o[2]=R[6]*x+R[7]*y+R[8]*z+tv[2];
        s = pr + 720 + h*12 + p*3; x=s[0]; y=s[1]; z=s[2];
        o = g_kpg + ((size_t)h*NT+i)*12 + p*3;
        o[0]=R[0]*x+R[1]*y+R[2]*z+tv[0];
        o[1]=R[3]*x+R[4]*y+R[5]*z+tv[1];
        o[2]=R[6]*x+R[7]*y+R[8]*z+tv[2];
    }
    for (int e = t; e < NH*8; e += 128) {
        int h = e/8, p = e%8;
        const float* s = pr + 864 + h*24 + p*3;
        float x=s[0], y=s[1], z=s[2];
        float* o = g_vpg + ((size_t)h*NT+i)*24 + p*3;
        o[0]=R[0]*x+R[1]*y+R[2]*z+tv[0];
        o[1]=R[3]*x+R[4]*y+R[5]*z+tv[1];
        o[2]=R[6]*x+R[7]*y+R[8]*z+tv[2];
    }
}

// ------------- pair bias v4: streaming, no data staging -------------
// Thread = one ij-row. 12 head accumulators in registers. Row streamed from
// global as float4 (lines fully reused via L1 across 8 k4 steps). Weights:
// warp-uniform broadcast LDS.128 from 6KB smem transpose. No barriers in the
// hot loop -> DRAM stays saturated; high occupancy.
__global__ __launch_bounds__(256) void bias_k(
    const float* __restrict__ pair, const float* __restrict__ Wpb,
    const float* __restrict__ bpb)
{
    __shared__ float wT[12][128];
    __shared__ float bb[12];
    const int tid = threadIdx.x;
    for (int e = tid; e < 12*128; e += 256) {
        int h = e >> 7, d = e & 127;
        wT[h][d] = Wpb[d*12 + h];
    }
    if (tid < 12) bb[tid] = bpb[tid];
    __syncthreads();

    const size_t row = (size_t)blockIdx.x * 256 + tid;
    const float4* prow = reinterpret_cast<const float4*>(pair) + row * 32;

    float a[12];
#pragma unroll
    for (int h = 0; h < 12; h++) a[h] = 0.f;

#pragma unroll 4
    for (int k4 = 0; k4 < 32; k4++) {
        float4 v = __ldg(&prow[k4]);
#pragma unroll
        for (int h = 0; h < 12; h++) {
            float4 w = *reinterpret_cast<const float4*>(&wT[h][k4*4]);
            a[h] += v.x*w.x + v.y*w.y + v.z*w.z + v.w*w.w;
        }
    }
    const size_t NTNT = (size_t)NT * NT;
#pragma unroll
    for (int h = 0; h < 12; h++)
        g_bias[(size_t)h*NTNT + row] = (a[h] + bb[h]) * PAIR_SCALE;
}

// ------------- fused attention: register accumulators -------------
#define PRS_OFF 0                    // [3][32][132]
#define ACC_OFF 12672                // [3][12][168]
#define PPS_OFF 18720                // [3][12][32]
#define QSS_OFF 19872
#define QPS_OFF 20448
#define MST_OFF 20880
#define LST_OFF 20916
#define FAC_OFF 20952
#define RS_OFF  20988
#define TV_OFF  21015
#define SMEM_FLOATS 21024

__global__ __launch_bounds__(384, 2) void attn_k(
    const float* __restrict__ pair, const float* __restrict__ rot,
    const float* __restrict__ trans, const float* __restrict__ pwts)
{
    extern __shared__ float sm[];
    float* prs  = sm + PRS_OFF;
    float* accs = sm + ACC_OFF;
    float* pps  = sm + PPS_OFF;
    float* qss  = sm + QSS_OFF;
    float* qps  = sm + QPS_OFF;
    float* mst  = sm + MST_OFF;
    float* lst  = sm + LST_OFF;
    float* facs = sm + FAC_OFF;
    float* Rs   = sm + RS_OFF;
    float* tvs  = sm + TV_OFF;

    const int i0 = blockIdx.x * TI;
    const int t  = threadIdx.x;
    const int h  = t >> 5, lane = t & 31;

    const int hg = t & 1;
    const int jq = (t >> 1) & 1;
    const int cc = (t >> 2) & 31;
    const int qq = t >> 7;
    const bool has_sp = (t < 360);
    const int q2  = t / 120;
    const int rm2 = t % 120;
    const int hh2 = rm2 / 10;
    const int c2  = rm2 % 10;
    const float* vbase;
    int vstride;
    if (c2 < 4) { vbase = g_vs  + (size_t)hh2*NT*16 + c2*4;     vstride = 16; }
    else        { vbase = g_vpg + (size_t)hh2*NT*24 + (c2-4)*4; vstride = 24; }

    float4 pacc[6];
#pragma unroll
    for (int m = 0; m < 6; m++) pacc[m] = make_float4(0.f,0.f,0.f,0.f);
    float4 spacc = make_float4(0.f,0.f,0.f,0.f);

    for (int e = t; e < TI*NH*16;  e += 384) {
        int q = e / (NH*16), rem = e % (NH*16);
        qss[e] = g_qs[((size_t)(rem/16)*NT + i0 + q)*16 + rem%16];
    }
    for (int e = t; e < TI*NH*12;  e += 384) {
        int q = e / (NH*12), rem = e % (NH*12);
        qps[e] = g_qpg[((size_t)(rem/12)*NT + i0 + q)*12 + rem%12];
    }
    if (t < TI*NH) { mst[t] = -1e30f; lst[t] = 0.f; }
    if (t < TI*9)  Rs[t]  = rot[(i0 + t/9)*9 + t%9];
    if (t < TI*3)  tvs[t] = trans[(i0 + t/3)*3 + t%3];
    __syncthreads();

    float wv = pwts[h];
    float pwh = (wv > 20.f) ? wv : log1pf(expf(wv));
    const float pscale = -0.5f * POINT_SCALE * pwh;

    for (int jt = 0; jt < NTILE; jt++) {
        const int j0 = jt * 32;
        for (int e = t; e < TI*32*32; e += 384) {
            int q = e >> 10, rem = e & 1023;
            int r = rem >> 5, c = rem & 31;
            float4 v = *reinterpret_cast<const float4*>(
                pair + ((size_t)(i0+q)*NT + j0 + r)*PD + c*4);
            *reinterpret_cast<float4*>(&prs[(q*32 + r)*132 + c*4]) = v;
        }
        {
            const int j = j0 + lane;
            // prefetch bias for all 3 queries early
            float bias_pf[TI];
#pragma unroll
            for (int q = 0; q < TI; q++)
                bias_pf[q] = __ldg(&g_bias[(size_t)h*NT*NT + (size_t)(i0+q)*NT + j]);
            const float4* kr = reinterpret_cast<const float4*>(g_ks  + ((size_t)h*NT + j)*16);
            const float4* kp = reinterpret_cast<const float4*>(g_kpg + ((size_t)h*NT + j)*12);
            float4 k0 = kr[0], k1 = kr[1], k2 = kr[2], k3 = kr[3];
            float4 p0 = kp[0], p1 = kp[1], p2 = kp[2];
#pragma unroll
            for (int q = 0; q < TI; q++) {
                const float4* qsv = reinterpret_cast<const float4*>(qss + (q*NH + h)*16);
                const float4* qpv = reinterpret_cast<const float4*>(qps + (q*NH + h)*12);
                float4 a0 = qsv[0], a1 = qsv[1], a2 = qsv[2], a3 = qsv[3];
                float s = a0.x*k0.x + a0.y*k0.y + a0.z*k0.z + a0.w*k0.w
                        + a1.x*k1.x + a1.y*k1.y + a1.z*k1.z + a1.w*k1.w
                        + a2.x*k2.x + a2.y*k2.y + a2.z*k2.z + a2.w*k2.w
                        + a3.x*k3.x + a3.y*k3.y + a3.z*k3.z + a3.w*k3.w;
                s *= SCALAR_SCALE;
                float4 b0 = qpv[0], b1 = qpv[1], b2 = qpv[2];
                float dx, dist = 0.f;
                dx = b0.x-p0.x; dist += dx*dx; dx = b0.y-p0.y; dist += dx*dx;
                dx = b0.z-p0.z; dist += dx*dx; dx = b0.w-p0.w; dist += dx*dx;
                dx = b1.x-p1.x; dist += dx*dx; dx = b1.y-p1.y; dist += dx*dx;
                dx = b1.z-p1.z; dist += dx*dx; dx = b1.w-p1.w; dist += dx*dx;
                dx = b2.x-p2.x; dist += dx*dx; dx = b2.y-p2.y; dist += dx*dx;
                dx = b2.z-p2.z; dist += dx*dx; dx = b2.w-p2.w; dist += dx*dx;
                s += pscale * dist;
                s += bias_pf[q];

                float mx = s;
                for (int o = 16; o; o >>= 1) mx = fmaxf(mx, __shfl_xor_sync(~0u, mx, o));
                float m_old = mst[q*NH + h];
                float m_new = fmaxf(m_old, mx);
                float p = __expf(s - m_new);
                pps[(q*NH + h)*32 + lane] = p;
                float ps = p;
                for (int o = 16; o; o >>= 1) ps += __shfl_xor_sync(~0u, ps, o);
                if (lane == 0) {
                    float f = __expf(m_old - m_new);
                    facs[q*NH + h] = f;
                    lst[q*NH + h] = lst[q*NH + h]*f + ps;
                    mst[q*NH + h] = m_new;
                }
                __syncwarp();
            }
        }
        __syncthreads();
        {
            const float* fq = facs + qq*NH + hg*6;
            float f0=fq[0], f1=fq[1], f2=fq[2], f3=fq[3], f4=fq[4], f5=fq[5];
            pacc[0].x*=f0; pacc[0].y*=f0; pacc[0].z*=f0; pacc[0].w*=f0;
            pacc[1].x*=f1; pacc[1].y*=f1; pacc[1].z*=f1; pacc[1].w*=f1;
            pacc[2].x*=f2; pacc[2].y*=f2; pacc[2].z*=f2; pacc[2].w*=f2;
            pacc[3].x*=f3; pacc[3].y*=f3; pacc[3].z*=f3; pacc[3].w*=f3;
            pacc[4].x*=f4; pacc[4].y*=f4; pacc[4].z*=f4; pacc[4].w*=f4;
            pacc[5].x*=f5; pacc[5].y*=f5; pacc[5].z*=f5; pacc[5].w*=f5;
            const float* pbase = pps + (qq*NH + hg*6)*32 + jq*16;
            const float* prow  = prs + (qq*32 + jq*16)*132 + cc*4;
#pragma unroll
            for (int jj = 0; jj < 16; jj++) {
                float4 v = *reinterpret_cast<const float4*>(prow + jj*132);
                float p0 = pbase[0*32+jj], p1 = pbase[1*32+jj], p2 = pbase[2*32+jj];
                float p3 = pbase[3*32+jj], p4 = pbase[4*32+jj], p5 = pbase[5*32+jj];
                pacc[0].x += p0*v.x; pacc[0].y += p0*v.y; pacc[0].z += p0*v.z; pacc[0].w += p0*v.w;
                pacc[1].x += p1*v.x; pacc[1].y += p1*v.y; pacc[1].z += p1*v.z; pacc[1].w += p1*v.w;
                pacc[2].x += p2*v.x; pacc[2].y += p2*v.y; pacc[2].z += p2*v.z; pacc[2].w += p2*v.w;
                pacc[3].x += p3*v.x; pacc[3].y += p3*v.y; pacc[3].z += p3*v.z; pacc[3].w += p3*v.w;
                pacc[4].x += p4*v.x; pacc[4].y += p4*v.y; pacc[4].z += p4*v.z; pacc[4].w += p4*v.w;
                pacc[5].x += p5*v.x; pacc[5].y += p5*v.y; pacc[5].z += p5*v.z; pacc[5].w += p5*v.w;
            }
        }
        if (has_sp) {
            float f = facs[q2*NH + hh2];
            spacc.x *= f; spacc.y *= f; spacc.z *= f; spacc.w *= f;
            const float* pph = pps + (q2*NH + hh2)*32;
            const float* src = vbase + (size_t)j0*vstride;
#pragma unroll 8
            for (int j = 0; j < 32; j++) {
                float p = pph[j];
                float4 v = *reinterpret_cast<const float4*>(src + (size_t)j*vstride);
                spacc.x += p*v.x; spacc.y += p*v.y; spacc.z += p*v.z; spacc.w += p*v.w;
            }
        }
        __syncthreads();
    }

    {
        int base = (qq*NH + hg*6)*168 + 40 + cc*4;
        if (jq == 0) {
#pragma unroll
            for (int m = 0; m < 6; m++)
                *reinterpret_cast<float4*>(accs + base + m*168) = pacc[m];
        }
        if (has_sp) {
            int off = (c2 < 4) ? c2*4 : 16 + (c2-4)*4;
            *reinterpret_cast<float4*>(accs + (q2*NH + hh2)*168 + off) = spacc;
        }
        __syncthreads();
        if (jq == 1) {
#pragma unroll
            for (int m = 0; m < 6; m++) {
                float4* p = reinterpret_cast<float4*>(accs + base + m*168);
                float4 a = *p;
                a.x += pacc[m].x; a.y += pacc[m].y; a.z += pacc[m].z; a.w += pacc[m].w;
                *p = a;
            }
        }
        __syncthreads();
    }

    for (int e = t; e < TI*NH*16; e += 384) {
        int q = e / (NH*16), rem = e % (NH*16);
        int hh = rem/16, d = rem%16;
        g_feats[(size_t)(i0+q)*FEAT + hh*16 + d] =
            accs[(q*NH+hh)*168 + d] / lst[q*NH+hh];
    }
    for (int e = t; e < TI*NH*8; e += 384) {
        int q = e / (NH*8), rem = e % (NH*8);
        int hh = rem/8, p = rem%8;
        float inv = 1.f / lst[q*NH+hh];
        const float* R = Rs + q*9;
        const float* tv = tvs + q*3;
        const float* ac = accs + (q*NH+hh)*168 + 16 + p*3;
        float gx = ac[0]*inv - tv[0];
        float gy = ac[1]*inv - tv[1];
        float gz = ac[2]*inv - tv[2];
        float lx = R[0]*gx + R[3]*gy + R[6]*gz;
        float ly = R[1]*gx + R[4]*gy + R[7]*gz;
        float lz = R[2]*gx + R[5]*gy + R[8]*gz;
        float* fo = g_feats + (size_t)(i0+q)*FEAT;
        fo[192 + hh*24 + p*3 + 0] = lx;
        fo[192 + hh*24 + p*3 + 1] = ly;
        fo[192 + hh*24 + p*3 + 2] = lz;
        fo[480 + hh*8 + p] = sqrtf(lx*lx + ly*ly + lz*lz + 1e-8f);
    }
    for (int e = t; e < TI*NH*PD; e += 384) {
        int q = e / (NH*PD), rem = e % (NH*PD);
        int hh = rem/PD, d = rem%PD;
        g_feats[(size_t)(i0+q)*FEAT + 576 + hh*PD + d] =
            accs[(q*NH+hh)*168 + 40 + d] / lst[q*NH+hh];
    }
}

// ------------- launch -------------
extern "C" void kernel_launch(void* const* d_in, const int* in_sizes, int n_in,
                              void* d_out, int out_size)
{
    (void)in_sizes; (void)n_in; (void)out_size;
    const float* x     = (const float*)d_in[0];
    const float* pair  = (const float*)d_in[1];
    const float* rot   = (const float*)d_in[2];
    const float* trans = (const float*)d_in[3];
    const float* Wq    = (const float*)d_in[4];
    const float* Wk    = (const float*)d_in[5];
    const float* Wv    = (const float*)d_in[6];
    const float* Wpq   = (const float*)d_in[7];
    const float* Wpk   = (const float*)d_in[8];
    const float* Wpv   = (const float*)d_in[9];
    const float* Wpb   = (const float*)d_in[10];
    const float* bpb   = (const float*)d_in[11];
    const float* pwts  = (const float*)d_in[12];
    const float* Wout  = (const float*)d_in[13];
    const float* bout  = (const float*)d_in[14];
    float* out = (float*)d_out;

    cudaFuncSetAttribute(attn_k, cudaFuncAttributeMaxDynamicSharedMemorySize,
                         SMEM_FLOATS * 4);

    void *p_wall, *p_proj, *p_feats, *p_part;
    cudaGetSymbolAddress(&p_wall,  g_wall);
    cudaGetSymbolAddress(&p_proj,  g_proj);
    cudaGetSymbolAddress(&p_feats, g_feats);
    cudaGetSymbolAddress(&p_part,  g_part);

    pack_w<<<(DIM*NPROJ + 255)/256, 256>>>(Wq, Wk, Wv, Wpq, Wpk, Wpv);
    {
        dim3 g(NPROJ/64, NT/64, 1);
        sgemm_sk<<<g, 128>>>(x, (const float*)p_wall, (float*)p_proj,
                             NT, NPROJ, DIM);
    }
    relayout<<<NT, 128>>>(rot, trans);
    bias_k<<<(NT*NT)/256, 256>>>(pair, Wpb, bpb);
    attn_k<<<NT/TI, 384, SMEM_FLOATS*4>>>(pair, rot, trans, pwts);
    {
        dim3 g(DIM/64, NT/64, SPLITK);
        sgemm_sk<<<g, 128>>>((const float*)p_feats, Wout, (float*)p_part,
                             NT, DIM, FEAT);
    }
    reduce_k<<<(NT*DIM + 255)/256, 256>>>(out, bout);
}

// round 8
// speedup vs baseline: 2.5987x; 1.0188x over previous
#include <cuda_runtime.h>
#include <math.h>
#include <stdint.h>
#include <stddef.h>

#define NT    768
#define NH    12
#define DIM   384
#define PD    128
#define FEAT  2112
#define NPROJ 1152
#define TI    3
#define NTILE 24
#define SPLITK 6

#define SCALAR_SCALE 0.14433756729740643f
#define POINT_SCALE  0.13608276348795434f
#define PAIR_SCALE   0.57735026918962584f

// ------------- device scratch -------------
__device__ __align__(16) float g_wall [DIM * NPROJ];
__device__ __align__(16) float g_proj [NT * NPROJ];
__device__ __align__(16) float g_qs   [NH * NT * 16];
__device__ __align__(16) float g_ks   [NH * NT * 16];
__device__ __align__(16) float g_vs   [NH * NT * 16];
__device__ __align__(16) float g_qpg  [NH * NT * 12];
__device__ __align__(16) float g_kpg  [NH * NT * 12];
__device__ __align__(16) float g_vpg  [NH * NT * 24];
__device__ __align__(16) float g_feats[(size_t)NT * FEAT];
__device__ __align__(16) float g_part [SPLITK * NT * DIM];

// ------------- pack weights -------------
__global__ __launch_bounds__(256) void pack_w(
    const float* __restrict__ Wq,  const float* __restrict__ Wk,
    const float* __restrict__ Wv,  const float* __restrict__ Wpq,
    const float* __restrict__ Wpk, const float* __restrict__ Wpv)
{
    int e = blockIdx.x * 256 + threadIdx.x;
    if (e >= DIM * NPROJ) return;
    int r = e / NPROJ, c = e % NPROJ;
    float v;
    if      (c < 192) v = Wq [r*192 + c];
    else if (c < 384) v = Wk [r*192 + (c-192)];
    else if (c < 576) v = Wv [r*192 + (c-384)];
    else if (c < 720) v = Wpq[r*144 + (c-576)];
    else if (c < 864) v = Wpk[r*144 + (c-720)];
    else              v = Wpv[r*288 + (c-864)];
    g_wall[e] = v;
}

// ------------- split-K SGEMM: 64x64 tile, TM=8 TN=4, 128 threads ----------
__global__ __launch_bounds__(128) void sgemm_sk(
    const float* __restrict__ A, const float* __restrict__ B,
    float* __restrict__ C, int M, int N, int K)
{
    __shared__ float As[16][64];
    __shared__ float Bs[16][68];
    const int tid = threadIdx.x;
    const int tx = tid & 15, ty = tid >> 4;
    const int row0 = blockIdx.y * 64, col0 = blockIdx.x * 64;
    const int kchunk = K / gridDim.z;
    const int kbeg = blockIdx.z * kchunk;

    float acc[8][4];
#pragma unroll
    for (int m = 0; m < 8; m++)
#pragma unroll
        for (int n = 0; n < 4; n++) acc[m][n] = 0.f;

    for (int k0 = kbeg; k0 < kbeg + kchunk; k0 += 16) {
        for (int e = tid; e < 256; e += 128) {
            int r = e >> 2, c4 = e & 3;
            float4 v = *reinterpret_cast<const float4*>(
                &A[(size_t)(row0+r)*K + k0 + c4*4]);
            As[c4*4+0][r] = v.x; As[c4*4+1][r] = v.y;
            As[c4*4+2][r] = v.z; As[c4*4+3][r] = v.w;
        }
        for (int e = tid; e < 256; e += 128) {
            int r = e >> 4, c4 = e & 15;
            *reinterpret_cast<float4*>(&Bs[r][c4*4]) =
                *reinterpret_cast<const float4*>(
                    &B[(size_t)(k0+r)*N + col0 + c4*4]);
        }
        __syncthreads();
#pragma unroll
        for (int kk = 0; kk < 16; kk++) {
            float a[8];
#pragma unroll
            for (int m = 0; m < 8; m++) a[m] = As[kk][ty*8 + m];
            float4 b = *reinterpret_cast<const float4*>(&Bs[kk][tx*4]);
#pragma unroll
            for (int m = 0; m < 8; m++) {
                acc[m][0] += a[m]*b.x; acc[m][1] += a[m]*b.y;
                acc[m][2] += a[m]*b.z; acc[m][3] += a[m]*b.w;
            }
        }
        __syncthreads();
    }
    float* Cz = C + (size_t)blockIdx.z * M * N;
#pragma unroll
    for (int m = 0; m < 8; m++) {
        int r = row0 + ty*8 + m;
        float4 v = make_float4(acc[m][0], acc[m][1], acc[m][2], acc[m][3]);
        *reinterpret_cast<float4*>(&Cz[(size_t)r*N + col0 + tx*4]) = v;
    }
}

// ------------- split-K reduce (+ output bias) -------------
__global__ __launch_bounds__(256) void reduce_k(
    float* __restrict__ out, const float* __restrict__ bout)
{
    int e = blockIdx.x * 256 + threadIdx.x;
    if (e >= NT * DIM) return;
    float s = 0.f;
#pragma unroll
    for (int z = 0; z < SPLITK; z++) s += g_part[(size_t)z*NT*DIM + e];
    out[e] = s + bout[e % DIM];
}

// ------------- relayout + rotate points to global frame -------------
__global__ __launch_bounds__(128) void relayout(
    const float* __restrict__ rot, const float* __restrict__ trans)
{
    const int i = blockIdx.x, t = threadIdx.x;
    __shared__ float R[9], tv[3];
    if (t < 9) R[t]  = rot[i*9 + t];
    if (t < 3) tv[t] = trans[i*3 + t];
    __syncthreads();
    const float* pr = g_proj + (size_t)i * NPROJ;
    for (int e = t; e < NH*16; e += 128) {
        int h = e/16, d = e%16;
        g_qs[((size_t)h*NT+i)*16+d] = pr[      h*16+d];
        g_ks[((size_t)h*NT+i)*16+d] = pr[192 + h*16+d];
        g_vs[((size_t)h*NT+i)*16+d] = pr[384 + h*16+d];
    }
    for (int e = t; e < NH*4; e += 128) {
        int h = e/4, p = e%4;
        const float* s = pr + 576 + h*12 + p*3;
        float x=s[0], y=s[1], z=s[2];
        float* o = g_qpg + ((size_t)h*NT+i)*12 + p*3;
        o[0]=R[0]*x+R[1]*y+R[2]*z+tv[0];
        o[1]=R[3]*x+R[4]*y+R[5]*z+tv[1];
        o[2]=R[6]*x+R[7]*y+R[8]*z+tv[2];
        s = pr + 720 + h*12 + p*3; x=s[0]; y=s[1]; z=s[2];
        o = g_kpg + ((size_t)h*NT+i)*12 + p*3;
        o[0]=R[0]*x+R[1]*y+R[2]*z+tv[0];
        o[1]=R[3]*x+R[4]*y+R[5]*z+tv[1];
        o[2]=R[6]*x+R[7]*y+R[8]*z+tv[2];
    }
    for (int e = t; e < NH*8; e += 128) {
        int h = e/8, p = e%8;
        const float* s = pr + 864 + h*24 + p*3;
        float x=s[0], y=s[1], z=s[2];
        float* o = g_vpg + ((size_t)h*NT+i)*24 + p*3;
        o[0]=R[0]*x+R[1]*y+R[2]*z+tv[0];
        o[1]=R[3]*x+R[4]*y+R[5]*z+tv[1];
        o[2]=R[6]*x+R[7]*y+R[8]*z+tv[2];
    }
}

// ------------- fused attention + pair-bias GEMM -------------
// Bias is computed per j-tile from the staged pair tile (prs), eliminating
// the separate bias kernel and its 302MB re-read of pairwise_repr.
#define PRS_OFF 0                    // [3][32][132]
#define ACC_OFF 12672                // [3][12][168]
#define PPS_OFF 18720                // [3][12][32]
#define QSS_OFF 19872
#define QPS_OFF 20448
#define MST_OFF 20880
#define LST_OFF 20916
#define FAC_OFF 20952
#define RS_OFF  20988
#define TV_OFF  21015
#define WT_OFF  21024                // [12][132] transposed Wpb
#define BB_OFF  22608                // [12]
#define BT_OFF  22620                // [3][12][32] bias tile
#define SMEM_FLOATS 23772

__global__ __launch_bounds__(384, 2) void attn_k(
    const float* __restrict__ pair, const float* __restrict__ rot,
    const float* __restrict__ trans, const float* __restrict__ pwts,
    const float* __restrict__ Wpb, const float* __restrict__ bpb)
{
    extern __shared__ float sm[];
    float* prs  = sm + PRS_OFF;
    float* accs = sm + ACC_OFF;
    float* pps  = sm + PPS_OFF;
    float* qss  = sm + QSS_OFF;
    float* qps  = sm + QPS_OFF;
    float* mst  = sm + MST_OFF;
    float* lst  = sm + LST_OFF;
    float* facs = sm + FAC_OFF;
    float* Rs   = sm + RS_OFF;
    float* tvs  = sm + TV_OFF;
    float* wTs  = sm + WT_OFF;
    float* bbs  = sm + BB_OFF;
    float* bts  = sm + BT_OFF;

    const int i0 = blockIdx.x * TI;
    const int t  = threadIdx.x;
    const int h  = t >> 5, lane = t & 31;

    // accumulate-phase roles
    const int hg = t & 1;
    const int jq = (t >> 1) & 1;
    const int cc = (t >> 2) & 31;
    const int qq = t >> 7;
    const bool has_sp = (t < 360);
    const int q2  = t / 120;
    const int rm2 = t % 120;
    const int hh2 = rm2 / 10;
    const int c2  = rm2 % 10;
    const float* vbase;
    int vstride;
    if (c2 < 4) { vbase = g_vs  + (size_t)hh2*NT*16 + c2*4;     vstride = 16; }
    else        { vbase = g_vpg + (size_t)hh2*NT*24 + (c2-4)*4; vstride = 24; }

    // bias-phase roles: thread = (pair row, head triple)
    const int brow = t >> 2;            // 0..95  (q*32 + r)
    const int bg   = t & 3;             // head group: heads 3bg..3bg+2

    float4 pacc[6];
#pragma unroll
    for (int m = 0; m < 6; m++) pacc[m] = make_float4(0.f,0.f,0.f,0.f);
    float4 spacc = make_float4(0.f,0.f,0.f,0.f);

    for (int e = t; e < TI*NH*16;  e += 384) {
        int q = e / (NH*16), rem = e % (NH*16);
        qss[e] = g_qs[((size_t)(rem/16)*NT + i0 + q)*16 + rem%16];
    }
    for (int e = t; e < TI*NH*12;  e += 384) {
        int q = e / (NH*12), rem = e % (NH*12);
        qps[e] = g_qpg[((size_t)(rem/12)*NT + i0 + q)*12 + rem%12];
    }
    for (int e = t; e < NH*PD; e += 384)          // Wpb transpose: wT[h][d]
        wTs[(e >> 7)*132 + (e & 127)] = Wpb[(e & 127)*12 + (e >> 7)];
    if (t < NH) bbs[t] = bpb[t];
    if (t < TI*NH) { mst[t] = -1e30f; lst[t] = 0.f; }
    if (t < TI*9)  Rs[t]  = rot[(i0 + t/9)*9 + t%9];
    if (t < TI*3)  tvs[t] = trans[(i0 + t/3)*3 + t%3];
    __syncthreads();

    float wv = pwts[h];
    float pwh = (wv > 20.f) ? wv : log1pf(expf(wv));
    const float pscale = -0.5f * POINT_SCALE * pwh;

    for (int jt = 0; jt < NTILE; jt++) {
        const int j0 = jt * 32;
        // ---- stage pair tiles for 3 queries (coalesced float4) ----
        for (int e = t; e < TI*32*32; e += 384) {
            int q = e >> 10, rem = e & 1023;
            int r = rem >> 5, c = rem & 31;
            float4 v = *reinterpret_cast<const float4*>(
                pair + ((size_t)(i0+q)*NT + j0 + r)*PD + c*4);
            *reinterpret_cast<float4*>(&prs[(q*32 + r)*132 + c*4]) = v;
        }
        __syncthreads();
        // ---- fused pair-bias: 3 head-dots per thread from smem ----
        {
            const float* prow = prs + brow*132;
            const float* w0 = wTs + (3*bg+0)*132;
            const float* w1 = wTs + (3*bg+1)*132;
            const float* w2 = wTs + (3*bg+2)*132;
            float b0 = 0.f, b1 = 0.f, b2 = 0.f;
#pragma unroll 8
            for (int k4 = 0; k4 < 32; k4++) {
                float4 v  = *reinterpret_cast<const float4*>(prow + k4*4);
                float4 wa = *reinterpret_cast<const float4*>(w0 + k4*4);
                float4 wb = *reinterpret_cast<const float4*>(w1 + k4*4);
                float4 wc = *reinterpret_cast<const float4*>(w2 + k4*4);
                b0 += v.x*wa.x + v.y*wa.y + v.z*wa.z + v.w*wa.w;
                b1 += v.x*wb.x + v.y*wb.y + v.z*wb.z + v.w*wb.w;
                b2 += v.x*wc.x + v.y*wc.y + v.z*wc.z + v.w*wc.w;
            }
            int bq = brow >> 5, br = brow & 31;
            bts[(bq*NH + 3*bg+0)*32 + br] = (b0 + bbs[3*bg+0]) * PAIR_SCALE;
            bts[(bq*NH + 3*bg+1)*32 + br] = (b1 + bbs[3*bg+1]) * PAIR_SCALE;
            bts[(bq*NH + 3*bg+2)*32 + br] = (b2 + bbs[3*bg+2]) * PAIR_SCALE;
        }
        __syncthreads();
        // ---- logits + online softmax (warp h, lane = j) ----
        {
            const int j = j0 + lane;
            const float4* kr = reinterpret_cast<const float4*>(g_ks  + ((size_t)h*NT + j)*16);
            const float4* kp = reinterpret_cast<const float4*>(g_kpg + ((size_t)h*NT + j)*12);
            float4 k0 = kr[0], k1 = kr[1], k2 = kr[2], k3 = kr[3];
            float4 p0 = kp[0], p1 = kp[1], p2 = kp[2];
#pragma unroll
            for (int q = 0; q < TI; q++) {
                const float4* qsv = reinterpret_cast<const float4*>(qss + (q*NH + h)*16);
                const float4* qpv = reinterpret_cast<const float4*>(qps + (q*NH + h)*12);
                float4 a0 = qsv[0], a1 = qsv[1], a2 = qsv[2], a3 = qsv[3];
                float s = a0.x*k0.x + a0.y*k0.y + a0.z*k0.z + a0.w*k0.w
                        + a1.x*k1.x + a1.y*k1.y + a1.z*k1.z + a1.w*k1.w
                        + a2.x*k2.x + a2.y*k2.y + a2.z*k2.z + a2.w*k2.w
                        + a3.x*k3.x + a3.y*k3.y + a3.z*k3.z + a3.w*k3.w;
                s *= SCALAR_SCALE;
                float4 b0 = qpv[0], b1 = qpv[1], b2 = qpv[2];
                float dx, dist = 0.f;
                dx = b0.x-p0.x; dist += dx*dx; dx = b0.y-p0.y; dist += dx*dx;
                dx = b0.z-p0.z; dist += dx*dx; dx = b0.w-p0.w; dist += dx*dx;
                dx = b1.x-p1.x; dist += dx*dx; dx = b1.y-p1.y; dist += dx*dx;
                dx = b1.z-p1.z; dist += dx*dx; dx = b1.w-p1.w; dist += dx*dx;
                dx = b2.x-p2.x; dist += dx*dx; dx = b2.y-p2.y; dist += dx*dx;
                dx = b2.z-p2.z; dist += dx*dx; dx = b2.w-p2.w; dist += dx*dx;
                s += pscale * dist;
                s += bts[(q*NH + h)*32 + lane];

                float mx = s;
                for (int o = 16; o; o >>= 1) mx = fmaxf(mx, __shfl_xor_sync(~0u, mx, o));
                float m_old = mst[q*NH + h];
                float m_new = fmaxf(m_old, mx);
                float p = __expf(s - m_new);
                pps[(q*NH + h)*32 + lane] = p;
                float ps = p;
                for (int o = 16; o; o >>= 1) ps += __shfl_xor_sync(~0u, ps, o);
                if (lane == 0) {
                    float f = __expf(m_old - m_new);
                    facs[q*NH + h] = f;
                    lst[q*NH + h] = lst[q*NH + h]*f + ps;
                    mst[q*NH + h] = m_new;
                }
                __syncwarp();
            }
        }
        __syncthreads();
        // ---- pair accumulate in registers: 1 LDS.128 feeds 24 FMA ----
        {
            const float* fq = facs + qq*NH + hg*6;
            float f0=fq[0], f1=fq[1], f2=fq[2], f3=fq[3], f4=fq[4], f5=fq[5];
            pacc[0].x*=f0; pacc[0].y*=f0; pacc[0].z*=f0; pacc[0].w*=f0;
            pacc[1].x*=f1; pacc[1].y*=f1; pacc[1].z*=f1; pacc[1].w*=f1;
            pacc[2].x*=f2; pacc[2].y*=f2; pacc[2].z*=f2; pacc[2].w*=f2;
            pacc[3].x*=f3; pacc[3].y*=f3; pacc[3].z*=f3; pacc[3].w*=f3;
            pacc[4].x*=f4; pacc[4].y*=f4; pacc[4].z*=f4; pacc[4].w*=f4;
            pacc[5].x*=f5; pacc[5].y*=f5; pacc[5].z*=f5; pacc[5].w*=f5;
            const float* pbase = pps + (qq*NH + hg*6)*32 + jq*16;
            const float* prow  = prs + (qq*32 + jq*16)*132 + cc*4;
#pragma unroll
            for (int jj = 0; jj < 16; jj++) {
                float4 v = *reinterpret_cast<const float4*>(prow + jj*132);
                float p0 = pbase[0*32+jj], p1 = pbase[1*32+jj], p2 = pbase[2*32+jj];
                float p3 = pbase[3*32+jj], p4 = pbase[4*32+jj], p5 = pbase[5*32+jj];
                pacc[0].x += p0*v.x; pacc[0].y += p0*v.y; pacc[0].z += p0*v.z; pacc[0].w += p0*v.w;
                pacc[1].x += p1*v.x; pacc[1].y += p1*v.y; pacc[1].z += p1*v.z; pacc[1].w += p1*v.w;
                pacc[2].x += p2*v.x; pacc[2].y += p2*v.y; pacc[2].z += p2*v.z; pacc[2].w += p2*v.w;
                pacc[3].x += p3*v.x; pacc[3].y += p3*v.y; pacc[3].z += p3*v.z; pacc[3].w += p3*v.w;
                pacc[4].x += p4*v.x; pacc[4].y += p4*v.y; pacc[4].z += p4*v.z; pacc[4].w += p4*v.w;
                pacc[5].x += p5*v.x; pacc[5].y += p5*v.y; pacc[5].z += p5*v.z; pacc[5].w += p5*v.w;
            }
        }
        if (has_sp) {
            float f = facs[q2*NH + hh2];
            spacc.x *= f; spacc.y *= f; spacc.z *= f; spacc.w *= f;
            const float* pph = pps + (q2*NH + hh2)*32;
            const float* src = vbase + (size_t)j0*vstride;
#pragma unroll 8
            for (int j = 0; j < 32; j++) {
                float p = pph[j];
                float4 v = *reinterpret_cast<const float4*>(src + (size_t)j*vstride);
                spacc.x += p*v.x; spacc.y += p*v.y; spacc.z += p*v.z; spacc.w += p*v.w;
            }
        }
        __syncthreads();
    }

    // ---- merge register accumulators ----
    {
        int base = (qq*NH + hg*6)*168 + 40 + cc*4;
        if (jq == 0) {
#pragma unroll
            for (int m = 0; m < 6; m++)
                *reinterpret_cast<float4*>(accs + base + m*168) = pacc[m];
        }
        if (has_sp) {
            int off = (c2 < 4) ? c2*4 : 16 + (c2-4)*4;
            *reinterpret_cast<float4*>(accs + (q2*NH + hh2)*168 + off) = spacc;
        }
        __syncthreads();
        if (jq == 1) {
#pragma unroll
            for (int m = 0; m < 6; m++) {
                float4* p = reinterpret_cast<float4*>(accs + base + m*168);
                float4 a = *p;
                a.x += pacc[m].x; a.y += pacc[m].y; a.z += pacc[m].z; a.w += pacc[m].w;
                *p = a;
            }
        }
        __syncthreads();
    }

    // ---- finalize ----
    for (int e = t; e < TI*NH*16; e += 384) {
        int q = e / (NH*16), rem = e % (NH*16);
        int hh = rem/16, d = rem%16;
        g_feats[(size_t)(i0+q)*FEAT + hh*16 + d] =
            accs[(q*NH+hh)*168 + d] / lst[q*NH+hh];
    }
    for (int e = t; e < TI*NH*8; e += 384) {
        int q = e / (NH*8), rem = e % (NH*8);
        int hh = rem/8, p = rem%8;
        float inv = 1.f / lst[q*NH+hh];
        const float* R = Rs + q*9;
        const float* tv = tvs + q*3;
        const float* ac = accs + (q*NH+hh)*168 + 16 + p*3;
        float gx = ac[0]*inv - tv[0];
        float gy = ac[1]*inv - tv[1];
        float gz = ac[2]*inv - tv[2];
        float lx = R[0]*gx + R[3]*gy + R[6]*gz;
        float ly = R[1]*gx + R[4]*gy + R[7]*gz;
        float lz = R[2]*gx + R[5]*gy + R[8]*gz;
        float* fo = g_feats + (size_t)(i0+q)*FEAT;
        fo[192 + hh*24 + p*3 + 0] = lx;
        fo[192 + hh*24 + p*3 + 1] = ly;
        fo[192 + hh*24 + p*3 + 2] = lz;
        fo[480 + hh*8 + p] = sqrtf(lx*lx + ly*ly + lz*lz + 1e-8f);
    }
    for (int e = t; e < TI*NH*PD; e += 384) {
        int q = e / (NH*PD), rem = e % (NH*PD);
        int hh = rem/PD, d = rem%PD;
        g_feats[(size_t)(i0+q)*FEAT + 576 + hh*PD + d] =
            accs[(q*NH+hh)*168 + 40 + d] / lst[q*NH+hh];
    }
}

// ------------- launch -------------
extern "C" void kernel_launch(void* const* d_in, const int* in_sizes, int n_in,
                              void* d_out, int out_size)
{
    (void)in_sizes; (void)n_in; (void)out_size;
    const float* x     = (const float*)d_in[0];
    const float* pair  = (const float*)d_in[1];
    const float* rot   = (const float*)d_in[2];
    const float* trans = (const float*)d_in[3];
    const float* Wq    = (const float*)d_in[4];
    const float* Wk    = (const float*)d_in[5];
    const float* Wv    = (const float*)d_in[6];
    const float* Wpq   = (const float*)d_in[7];
    const float* Wpk   = (const float*)d_in[8];
    const float* Wpv   = (const float*)d_in[9];
    const float* Wpb   = (const float*)d_in[10];
    const float* bpb   = (const float*)d_in[11];
    const float* pwts  = (const float*)d_in[12];
    const float* Wout  = (const float*)d_in[13];
    const float* bout  = (const float*)d_in[14];
    float* out = (float*)d_out;

    cudaFuncSetAttribute(attn_k, cudaFuncAttributeMaxDynamicSharedMemorySize,
                         SMEM_FLOATS * 4);

    void *p_wall, *p_proj, *p_feats, *p_part;
    cudaGetSymbolAddress(&p_wall,  g_wall);
    cudaGetSymbolAddress(&p_proj,  g_proj);
    cudaGetSymbolAddress(&p_feats, g_feats);
    cudaGetSymbolAddress(&p_part,  g_part);

    pack_w<<<(DIM*NPROJ + 255)/256, 256>>>(Wq, Wk, Wv, Wpq, Wpk, Wpv);
    {
        dim3 g(NPROJ/64, NT/64, 1);
        sgemm_sk<<<g, 128>>>(x, (const float*)p_wall, (float*)p_proj,
                             NT, NPROJ, DIM);
    }
    relayout<<<NT, 128>>>(rot, trans);
    attn_k<<<NT/TI, 384, SMEM_FLOATS*4>>>(pair, rot, trans, pwts, Wpb, bpb);
    {
        dim3 g(DIM/64, NT/64, SPLITK);
        sgemm_sk<<<g, 128>>>((const float*)p_feats, Wout, (float*)p_part,
                             NT, DIM, FEAT);
    }
    reduce_k<<<(NT*DIM + 255)/256, 256>>>(out, bout);
}

// round 9
// speedup vs baseline: 2.9066x; 1.1185x over previous
#include <cuda_runtime.h>
#include <math.h>
#include <stdint.h>
#include <stddef.h>

#define NT    768
#define NH    12
#define DIM   384
#define PD    128
#define FEAT  2112
#define NPROJ 1152
#define TI    3
#define NTILE 24
#define SPLITK 6

#define SCALAR_SCALE 0.14433756729740643f
#define POINT_SCALE  0.13608276348795434f
#define PAIR_SCALE   0.57735026918962584f

// ------------- device scratch -------------
__device__ __align__(16) float g_wall [DIM * NPROJ];
__device__ __align__(16) float g_proj [NT * NPROJ];
__device__ __align__(16) float g_qs   [NH * NT * 16];
__device__ __align__(16) float g_ks   [NH * NT * 16];
__device__ __align__(16) float g_vs   [NH * NT * 16];
__device__ __align__(16) float g_qpg  [NH * NT * 12];
__device__ __align__(16) float g_kpg  [NH * NT * 12];
__device__ __align__(16) float g_vpg  [NH * NT * 24];
__device__ __align__(16) float g_feats[(size_t)NT * FEAT];
__device__ __align__(16) float g_part [SPLITK * NT * DIM];

// ------------- pack weights -------------
__global__ __launch_bounds__(256) void pack_w(
    const float* __restrict__ Wq,  const float* __restrict__ Wk,
    const float* __restrict__ Wv,  const float* __restrict__ Wpq,
    const float* __restrict__ Wpk, const float* __restrict__ Wpv)
{
    int e = blockIdx.x * 256 + threadIdx.x;
    if (e >= DIM * NPROJ) return;
    int r = e / NPROJ, c = e % NPROJ;
    float v;
    if      (c < 192) v = Wq [r*192 + c];
    else if (c < 384) v = Wk [r*192 + (c-192)];
    else if (c < 576) v = Wv [r*192 + (c-384)];
    else if (c < 720) v = Wpq[r*144 + (c-576)];
    else if (c < 864) v = Wpk[r*144 + (c-720)];
    else              v = Wpv[r*288 + (c-864)];
    g_wall[e] = v;
}

// ------------- split-K SGEMM: 64x64 tile, TM=8 TN=4, 128 threads ----------
__global__ __launch_bounds__(128) void sgemm_sk(
    const float* __restrict__ A, const float* __restrict__ B,
    float* __restrict__ C, int M, int N, int K)
{
    __shared__ float As[16][64];
    __shared__ float Bs[16][68];
    const int tid = threadIdx.x;
    const int tx = tid & 15, ty = tid >> 4;
    const int row0 = blockIdx.y * 64, col0 = blockIdx.x * 64;
    const int kchunk = K / gridDim.z;
    const int kbeg = blockIdx.z * kchunk;

    float acc[8][4];
#pragma unroll
    for (int m = 0; m < 8; m++)
#pragma unroll
        for (int n = 0; n < 4; n++) acc[m][n] = 0.f;

    for (int k0 = kbeg; k0 < kbeg + kchunk; k0 += 16) {
        for (int e = tid; e < 256; e += 128) {
            int r = e >> 2, c4 = e & 3;
            float4 v = *reinterpret_cast<const float4*>(
                &A[(size_t)(row0+r)*K + k0 + c4*4]);
            As[c4*4+0][r] = v.x; As[c4*4+1][r] = v.y;
            As[c4*4+2][r] = v.z; As[c4*4+3][r] = v.w;
        }
        for (int e = tid; e < 256; e += 128) {
            int r = e >> 4, c4 = e & 15;
            *reinterpret_cast<float4*>(&Bs[r][c4*4]) =
                *reinterpret_cast<const float4*>(
                    &B[(size_t)(k0+r)*N + col0 + c4*4]);
        }
        __syncthreads();
#pragma unroll
        for (int kk = 0; kk < 16; kk++) {
            float a[8];
#pragma unroll
            for (int m = 0; m < 8; m++) a[m] = As[kk][ty*8 + m];
            float4 b = *reinterpret_cast<const float4*>(&Bs[kk][tx*4]);
#pragma unroll
            for (int m = 0; m < 8; m++) {
                acc[m][0] += a[m]*b.x; acc[m][1] += a[m]*b.y;
                acc[m][2] += a[m]*b.z; acc[m][3] += a[m]*b.w;
            }
        }
        __syncthreads();
    }
    float* Cz = C + (size_t)blockIdx.z * M * N;
#pragma unroll
    for (int m = 0; m < 8; m++) {
        int r = row0 + ty*8 + m;
        float4 v = make_float4(acc[m][0], acc[m][1], acc[m][2], acc[m][3]);
        *reinterpret_cast<float4*>(&Cz[(size_t)r*N + col0 + tx*4]) = v;
    }
}

// ------------- split-K reduce (+ output bias) -------------
__global__ __launch_bounds__(256) void reduce_k(
    float* __restrict__ out, const float* __restrict__ bout)
{
    int e = blockIdx.x * 256 + threadIdx.x;
    if (e >= NT * DIM) return;
    float s = 0.f;
#pragma unroll
    for (int z = 0; z < SPLITK; z++) s += g_part[(size_t)z*NT*DIM + e];
    out[e] = s + bout[e % DIM];
}

// ------------- relayout + rotate points to global frame -------------
__global__ __launch_bounds__(128) void relayout(
    const float* __restrict__ rot, const float* __restrict__ trans)
{
    const int i = blockIdx.x, t = threadIdx.x;
    __shared__ float R[9], tv[3];
    if (t < 9) R[t]  = rot[i*9 + t];
    if (t < 3) tv[t] = trans[i*3 + t];
    __syncthreads();
    const float* pr = g_proj + (size_t)i * NPROJ;
    for (int e = t; e < NH*16; e += 128) {
        int h = e/16, d = e%16;
        g_qs[((size_t)h*NT+i)*16+d] = pr[      h*16+d];
        g_ks[((size_t)h*NT+i)*16+d] = pr[192 + h*16+d];
        g_vs[((size_t)h*NT+i)*16+d] = pr[384 + h*16+d];
    }
    for (int e = t; e < NH*4; e += 128) {
        int h = e/4, p = e%4;
        const float* s = pr + 576 + h*12 + p*3;
        float x=s[0], y=s[1], z=s[2];
        float* o = g_qpg + ((size_t)h*NT+i)*12 + p*3;
        o[0]=R[0]*x+R[1]*y+R[2]*z+tv[0];
        o[1]=R[3]*x+R[4]*y+R[5]*z+tv[1];
        o[2]=R[6]*x+R[7]*y+R[8]*z+tv[2];
        s = pr + 720 + h*12 + p*3; x=s[0]; y=s[1]; z=s[2];
        o = g_kpg + ((size_t)h*NT+i)*12 + p*3;
        o[0]=R[0]*x+R[1]*y+R[2]*z+tv[0];
        o[1]=R[3]*x+R[4]*y+R[5]*z+tv[1];
        o[2]=R[6]*x+R[7]*y+R[8]*z+tv[2];
    }
    for (int e = t; e < NH*8; e += 128) {
        int h = e/8, p = e%8;
        const float* s = pr + 864 + h*24 + p*3;
        float x=s[0], y=s[1], z=s[2];
        float* o = g_vpg + ((size_t)h*NT+i)*24 + p*3;
        o[0]=R[0]*x+R[1]*y+R[2]*z+tv[0];
        o[1]=R[3]*x+R[4]*y+R[5]*z+tv[1];
        o[2]=R[6]*x+R[7]*y+R[8]*z+tv[2];
    }
}

// ------------- fused attention + pair-bias GEMM (bank-tuned) -------------
#define PRS_OFF 0                    // [3][32][132]
#define ACC_OFF 12672                // [3][12][168]
#define PPS_OFF 18720                // [3][12] rows, stride 33
#define QSS_OFF 19908
#define QPS_OFF 20484
#define MST_OFF 20916
#define LST_OFF 20952
#define FAC_OFF 20988
#define RS_OFF  21024
#define TV_OFF  21051
#define WT_OFF  21060                // [12][132] transposed Wpb
#define BB_OFF  22644                // [12]
#define BT_OFF  22656                // [3][12] rows, stride 33
#define SMEM_FLOATS 23844

__global__ __launch_bounds__(384, 2) void attn_k(
    const float* __restrict__ pair, const float* __restrict__ rot,
    const float* __restrict__ trans, const float* __restrict__ pwts,
    const float* __restrict__ Wpb, const float* __restrict__ bpb)
{
    extern __shared__ float sm[];
    float* prs  = sm + PRS_OFF;
    float* accs = sm + ACC_OFF;
    float* pps  = sm + PPS_OFF;
    float* qss  = sm + QSS_OFF;
    float* qps  = sm + QPS_OFF;
    float* mst  = sm + MST_OFF;
    float* lst  = sm + LST_OFF;
    float* facs = sm + FAC_OFF;
    float* Rs   = sm + RS_OFF;
    float* tvs  = sm + TV_OFF;
    float* wTs  = sm + WT_OFF;
    float* bbs  = sm + BB_OFF;
    float* bts  = sm + BT_OFF;

    const int i0 = blockIdx.x * TI;
    const int t  = threadIdx.x;
    const int h  = t >> 5, lane = t & 31;

    // pair-accumulate roles
    const int hg = t & 1;
    const int jq = (t >> 1) & 1;
    const int cc = (t >> 2) & 31;
    const int qq = t >> 7;
    // scalar/point roles: q-triples adjacent so V loads broadcast 3-way
    const bool has_sp = (t < 360);
    const int q2  = t % 3;
    const int u3  = t / 3;          // 0..119
    const int hh2 = u3 / 10;
    const int c2  = u3 % 10;
    const float* vbase;
    int vstride;
    if (c2 < 4) { vbase = g_vs  + (size_t)hh2*NT*16 + c2*4;     vstride = 16; }
    else        { vbase = g_vpg + (size_t)hh2*NT*24 + (c2-4)*4; vstride = 24; }
    // bias roles: 96 threads, thread = (rowgroup rg, head-triple bg), rows rg+24k
    const int rg = t >> 2;          // 0..23 (for t<96)
    const int bg = t & 3;

    float4 pacc[6];
#pragma unroll
    for (int m = 0; m < 6; m++) pacc[m] = make_float4(0.f,0.f,0.f,0.f);
    float4 spacc = make_float4(0.f,0.f,0.f,0.f);

    for (int e = t; e < TI*NH*16;  e += 384) {
        int q = e / (NH*16), rem = e % (NH*16);
        qss[e] = g_qs[((size_t)(rem/16)*NT + i0 + q)*16 + rem%16];
    }
    for (int e = t; e < TI*NH*12;  e += 384) {
        int q = e / (NH*12), rem = e % (NH*12);
        qps[e] = g_qpg[((size_t)(rem/12)*NT + i0 + q)*12 + rem%12];
    }
    for (int e = t; e < NH*PD; e += 384)
        wTs[(e >> 7)*132 + (e & 127)] = Wpb[(e & 127)*12 + (e >> 7)];
    if (t < NH) bbs[t] = bpb[t];
    if (t < TI*NH) { mst[t] = -1e30f; lst[t] = 0.f; }
    if (t < TI*9)  Rs[t]  = rot[(i0 + t/9)*9 + t%9];
    if (t < TI*3)  tvs[t] = trans[(i0 + t/3)*3 + t%3];
    __syncthreads();

    float wv = pwts[h];
    float pwh = (wv > 20.f) ? wv : log1pf(expf(wv));
    const float pscale = -0.5f * POINT_SCALE * pwh;

    for (int jt = 0; jt < NTILE; jt++) {
        const int j0 = jt * 32;
        // ---- stage pair tiles (coalesced float4) ----
        for (int e = t; e < TI*32*32; e += 384) {
            int q = e >> 10, rem = e & 1023;
            int r = rem >> 5, c = rem & 31;
            float4 v = *reinterpret_cast<const float4*>(
                pair + ((size_t)(i0+q)*NT + j0 + r)*PD + c*4);
            *reinterpret_cast<float4*>(&prs[(q*32 + r)*132 + c*4]) = v;
        }
        __syncthreads();
        // ---- fused pair-bias: 96 threads x (4 strided rows x 3 heads) ----
        if (t < 96) {
            const float* w0 = wTs + (3*bg+0)*132;
            const float* w1 = wTs + (3*bg+1)*132;
            const float* w2 = wTs + (3*bg+2)*132;
            float b[4][3];
#pragma unroll
            for (int r = 0; r < 4; r++)
#pragma unroll
                for (int k = 0; k < 3; k++) b[r][k] = 0.f;
#pragma unroll 4
            for (int k4 = 0; k4 < 32; k4++) {
                float4 wa = *reinterpret_cast<const float4*>(w0 + k4*4);
                float4 wb = *reinterpret_cast<const float4*>(w1 + k4*4);
                float4 wc = *reinterpret_cast<const float4*>(w2 + k4*4);
#pragma unroll
                for (int r = 0; r < 4; r++) {
                    float4 v = *reinterpret_cast<const float4*>(
                        &prs[(rg + 24*r)*132 + k4*4]);
                    b[r][0] += v.x*wa.x + v.y*wa.y + v.z*wa.z + v.w*wa.w;
                    b[r][1] += v.x*wb.x + v.y*wb.y + v.z*wb.z + v.w*wb.w;
                    b[r][2] += v.x*wc.x + v.y*wc.y + v.z*wc.z + v.w*wc.w;
                }
            }
#pragma unroll
            for (int r = 0; r < 4; r++) {
                int row = rg + 24*r;
                int bq = row >> 5, br = row & 31;
#pragma unroll
                for (int k = 0; k < 3; k++)
                    bts[(bq*NH + 3*bg+k)*33 + br] =
                        (b[r][k] + bbs[3*bg+k]) * PAIR_SCALE;
            }
        }
        __syncthreads();
        // ---- logits + online softmax (warp h, lane = j) ----
        {
            const int j = j0 + lane;
            const float4* kr = reinterpret_cast<const float4*>(g_ks  + ((size_t)h*NT + j)*16);
            const float4* kp = reinterpret_cast<const float4*>(g_kpg + ((size_t)h*NT + j)*12);
            float4 k0 = kr[0], k1 = kr[1], k2 = kr[2], k3 = kr[3];
            float4 p0 = kp[0], p1 = kp[1], p2 = kp[2];
#pragma unroll
            for (int q = 0; q < TI; q++) {
                const float4* qsv = reinterpret_cast<const float4*>(qss + (q*NH + h)*16);
                const float4* qpv = reinterpret_cast<const float4*>(qps + (q*NH + h)*12);
                float4 a0 = qsv[0], a1 = qsv[1], a2 = qsv[2], a3 = qsv[3];
                float s = a0.x*k0.x + a0.y*k0.y + a0.z*k0.z + a0.w*k0.w
                        + a1.x*k1.x + a1.y*k1.y + a1.z*k1.z + a1.w*k1.w
                        + a2.x*k2.x + a2.y*k2.y + a2.z*k2.z + a2.w*k2.w
                        + a3.x*k3.x + a3.y*k3.y + a3.z*k3.z + a3.w*k3.w;
                s *= SCALAR_SCALE;
                float4 b0 = qpv[0], b1 = qpv[1], b2 = qpv[2];
                float dx, dist = 0.f;
                dx = b0.x-p0.x; dist += dx*dx; dx = b0.y-p0.y; dist += dx*dx;
                dx = b0.z-p0.z; dist += dx*dx; dx = b0.w-p0.w; dist += dx*dx;
                dx = b1.x-p1.x; dist += dx*dx; dx = b1.y-p1.y; dist += dx*dx;
                dx = b1.z-p1.z; dist += dx*dx; dx = b1.w-p1.w; dist += dx*dx;
                dx = b2.x-p2.x; dist += dx*dx; dx = b2.y-p2.y; dist += dx*dx;
                dx = b2.z-p2.z; dist += dx*dx; dx = b2.w-p2.w; dist += dx*dx;
                s += pscale * dist;
                s += bts[(q*NH + h)*33 + lane];

                float mx = s;
                for (int o = 16; o; o >>= 1) mx = fmaxf(mx, __shfl_xor_sync(~0u, mx, o));
                float m_old = mst[q*NH + h];
                float m_new = fmaxf(m_old, mx);
                float p = __expf(s - m_new);
                pps[(q*NH + h)*33 + lane] = p;
                float ps = p;
                for (int o = 16; o; o >>= 1) ps += __shfl_xor_sync(~0u, ps, o);
                if (lane == 0) {
                    float f = __expf(m_old - m_new);
                    facs[q*NH + h] = f;
                    lst[q*NH + h] = lst[q*NH + h]*f + ps;
                    mst[q*NH + h] = m_new;
                }
                __syncwarp();
            }
        }
        __syncthreads();
        // ---- pair accumulate in registers ----
        {
            const float* fq = facs + qq*NH + hg*6;
            float f0=fq[0], f1=fq[1], f2=fq[2], f3=fq[3], f4=fq[4], f5=fq[5];
            pacc[0].x*=f0; pacc[0].y*=f0; pacc[0].z*=f0; pacc[0].w*=f0;
            pacc[1].x*=f1; pacc[1].y*=f1; pacc[1].z*=f1; pacc[1].w*=f1;
            pacc[2].x*=f2; pacc[2].y*=f2; pacc[2].z*=f2; pacc[2].w*=f2;
            pacc[3].x*=f3; pacc[3].y*=f3; pacc[3].z*=f3; pacc[3].w*=f3;
            pacc[4].x*=f4; pacc[4].y*=f4; pacc[4].z*=f4; pacc[4].w*=f4;
            pacc[5].x*=f5; pacc[5].y*=f5; pacc[5].z*=f5; pacc[5].w*=f5;
            const float* pbase = pps + (qq*NH + hg*6)*33 + jq*16;
            const float* prow  = prs + (qq*32 + jq*16)*132 + cc*4;
#pragma unroll
            for (int jj = 0; jj < 16; jj++) {
                float4 v = *reinterpret_cast<const float4*>(prow + jj*132);
                float p0 = pbase[0*33+jj], p1 = pbase[1*33+jj], p2 = pbase[2*33+jj];
                float p3 = pbase[3*33+jj], p4 = pbase[4*33+jj], p5 = pbase[5*33+jj];
                pacc[0].x += p0*v.x; pacc[0].y += p0*v.y; pacc[0].z += p0*v.z; pacc[0].w += p0*v.w;
                pacc[1].x += p1*v.x; pacc[1].y += p1*v.y; pacc[1].z += p1*v.z; pacc[1].w += p1*v.w;
                pacc[2].x += p2*v.x; pacc[2].y += p2*v.y; pacc[2].z += p2*v.z; pacc[2].w += p2*v.w;
                pacc[3].x += p3*v.x; pacc[3].y += p3*v.y; pacc[3].z += p3*v.z; pacc[3].w += p3*v.w;
                pacc[4].x += p4*v.x; pacc[4].y += p4*v.y; pacc[4].z += p4*v.z; pacc[4].w += p4*v.w;
                pacc[5].x += p5*v.x; pacc[5].y += p5*v.y; pacc[5].z += p5*v.z; pacc[5].w += p5*v.w;
            }
        }
        // ---- scalar/point accumulate (V loads broadcast across q-triples) ----
        if (has_sp) {
            float f = facs[q2*NH + hh2];
            spacc.x *= f; spacc.y *= f; spacc.z *= f; spacc.w *= f;
            const float* pph = pps + (q2*NH + hh2)*33;
            const float* src = vbase + (size_t)j0*vstride;
#pragma unroll 8
            for (int j = 0; j < 32; j++) {
                float p = pph[j];
                float4 v = *reinterpret_cast<const float4*>(src + (size_t)j*vstride);
                spacc.x += p*v.x; spacc.y += p*v.y; spacc.z += p*v.z; spacc.w += p*v.w;
            }
        }
        __syncthreads();
    }

    // ---- merge register accumulators ----
    {
        int base = (qq*NH + hg*6)*168 + 40 + cc*4;
        if (jq == 0) {
#pragma unroll
            for (int m = 0; m < 6; m++)
                *reinterpret_cast<float4*>(accs + base + m*168) = pacc[m];
        }
        if (has_sp) {
            int off = (c2 < 4) ? c2*4 : 16 + (c2-4)*4;
            *reinterpret_cast<float4*>(accs + (q2*NH + hh2)*168 + off) = spacc;
        }
        __syncthreads();
        if (jq == 1) {
#pragma unroll
            for (int m = 0; m < 6; m++) {
                float4* p = reinterpret_cast<float4*>(accs + base + m*168);
                float4 a = *p;
                a.x += pacc[m].x; a.y += pacc[m].y; a.z += pacc[m].z; a.w += pacc[m].w;
                *p = a;
            }
        }
        __syncthreads();
    }

    // ---- finalize ----
    for (int e = t; e < TI*NH*16; e += 384) {
        int q = e / (NH*16), rem = e % (NH*16);
        int hh = rem/16, d = rem%16;
        g_feats[(size_t)(i0+q)*FEAT + hh*16 + d] =
            accs[(q*NH+hh)*168 + d] / lst[q*NH+hh];
    }
    for (int e = t; e < TI*NH*8; e += 384) {
        int q = e / (NH*8), rem = e % (NH*8);
        int hh = rem/8, p = rem%8;
        float inv = 1.f / lst[q*NH+hh];
        const float* R = Rs + q*9;
        const float* tv = tvs + q*3;
        const float* ac = accs + (q*NH+hh)*168 + 16 + p*3;
        float gx = ac[0]*inv - tv[0];
        float gy = ac[1]*inv - tv[1];
        float gz = ac[2]*inv - tv[2];
        float lx = R[0]*gx + R[3]*gy + R[6]*gz;
        float ly = R[1]*gx + R[4]*gy + R[7]*gz;
        float lz = R[2]*gx + R[5]*gy + R[8]*gz;
        float* fo = g_feats + (size_t)(i0+q)*FEAT;
        fo[192 + hh*24 + p*3 + 0] = lx;
        fo[192 + hh*24 + p*3 + 1] = ly;
        fo[192 + hh*24 + p*3 + 2] = lz;
        fo[480 + hh*8 + p] = sqrtf(lx*lx + ly*ly + lz*lz + 1e-8f);
    }
    for (int e = t; e < TI*NH*PD; e += 384) {
        int q = e / (NH*PD), rem = e % (NH*PD);
        int hh = rem/PD, d = rem%PD;
        g_feats[(size_t)(i0+q)*FEAT + 576 + hh*PD + d] =
            accs[(q*NH+hh)*168 + 40 + d] / lst[q*NH+hh];
    }
}

// ------------- launch -------------
extern "C" void kernel_launch(void* const* d_in, const int* in_sizes, int n_in,
                              void* d_out, int out_size)
{
    (void)in_sizes; (void)n_in; (void)out_size;
    const float* x     = (const float*)d_in[0];
    const float* pair  = (const float*)d_in[1];
    const float* rot   = (const float*)d_in[2];
    const float* trans = (const float*)d_in[3];
    const float* Wq    = (const float*)d_in[4];
    const float* Wk    = (const float*)d_in[5];
    const float* Wv    = (const float*)d_in[6];
    const float* Wpq   = (const float*)d_in[7];
    const float* Wpk   = (const float*)d_in[8];
    const float* Wpv   = (const float*)d_in[9];
    const float* Wpb   = (const float*)d_in[10];
    const float* bpb   = (const float*)d_in[11];
    const float* pwts  = (const float*)d_in[12];
    const float* Wout  = (const float*)d_in[13];
    const float* bout  = (const float*)d_in[14];
    float* out = (float*)d_out;

    cudaFuncSetAttribute(attn_k, cudaFuncAttributeMaxDynamicSharedMemorySize,
                         SMEM_FLOATS * 4);

    void *p_wall, *p_proj, *p_feats, *p_part;
    cudaGetSymbolAddress(&p_wall,  g_wall);
    cudaGetSymbolAddress(&p_proj,  g_proj);
    cudaGetSymbolAddress(&p_feats, g_feats);
    cudaGetSymbolAddress(&p_part,  g_part);

    pack_w<<<(DIM*NPROJ + 255)/256, 256>>>(Wq, Wk, Wv, Wpq, Wpk, Wpv);
    {
        dim3 g(NPROJ/64, NT/64, 1);
        sgemm_sk<<<g, 128>>>(x, (const float*)p_wall, (float*)p_proj,
                             NT, NPROJ, DIM);
    }
    relayout<<<NT, 128>>>(rot, trans);
    attn_k<<<NT/TI, 384, SMEM_FLOATS*4>>>(pair, rot, trans, pwts, Wpb, bpb);
    {
        dim3 g(DIM/64, NT/64, SPLITK);
        sgemm_sk<<<g, 128>>>((const float*)p_feats, Wout, (float*)p_part,
                             NT, DIM, FEAT);
    }
    reduce_k<<<(NT*DIM + 255)/256, 256>>>(out, bout);
}

// round 10
// speedup vs baseline: 2.9412x; 1.0119x over previous
#include <cuda_runtime.h>
#include <math.h>
#include <stdint.h>
#include <stddef.h>

#define NT    768
#define NH    12
#define DIM   384
#define PD    128
#define FEAT  2112
#define NPROJ 1152
#define TI    3
#define NTILE 24
#define SPLITK 6

#define SCALAR_SCALE 0.14433756729740643f
#define POINT_SCALE  0.13608276348795434f
#define PAIR_SCALE   0.57735026918962584f

// ------------- device scratch -------------
__device__ __align__(16) float g_wall [DIM * NPROJ];
__device__ __align__(16) float g_proj [NT * NPROJ];
__device__ __align__(16) float g_qs   [NH * NT * 16];
__device__ __align__(16) float g_ks   [NH * NT * 16];
__device__ __align__(16) float g_vs   [NH * NT * 16];
__device__ __align__(16) float g_qpg  [NH * NT * 12];
__device__ __align__(16) float g_kpg  [NH * NT * 12];
__device__ __align__(16) float g_vpg  [NH * NT * 24];
__device__ __align__(16) float g_feats[(size_t)NT * FEAT];
__device__ __align__(16) float g_part [SPLITK * NT * DIM];

// ------------- pack weights -------------
__global__ __launch_bounds__(256) void pack_w(
    const float* __restrict__ Wq,  const float* __restrict__ Wk,
    const float* __restrict__ Wv,  const float* __restrict__ Wpq,
    const float* __restrict__ Wpk, const float* __restrict__ Wpv)
{
    int e = blockIdx.x * 256 + threadIdx.x;
    if (e >= DIM * NPROJ) return;
    int r = e / NPROJ, c = e % NPROJ;
    float v;
    if      (c < 192) v = Wq [r*192 + c];
    else if (c < 384) v = Wk [r*192 + (c-192)];
    else if (c < 576) v = Wv [r*192 + (c-384)];
    else if (c < 720) v = Wpq[r*144 + (c-576)];
    else if (c < 864) v = Wpk[r*144 + (c-720)];
    else              v = Wpv[r*288 + (c-864)];
    g_wall[e] = v;
}

// ------------- split-K SGEMM: 64x64 tile, TM=8 TN=4, 128 threads ----------
__global__ __launch_bounds__(128) void sgemm_sk(
    const float* __restrict__ A, const float* __restrict__ B,
    float* __restrict__ C, int M, int N, int K)
{
    __shared__ float As[16][64];
    __shared__ float Bs[16][68];
    const int tid = threadIdx.x;
    const int tx = tid & 15, ty = tid >> 4;
    const int row0 = blockIdx.y * 64, col0 = blockIdx.x * 64;
    const int kchunk = K / gridDim.z;
    const int kbeg = blockIdx.z * kchunk;

    float acc[8][4];
#pragma unroll
    for (int m = 0; m < 8; m++)
#pragma unroll
        for (int n = 0; n < 4; n++) acc[m][n] = 0.f;

    for (int k0 = kbeg; k0 < kbeg + kchunk; k0 += 16) {
        for (int e = tid; e < 256; e += 128) {
            int r = e >> 2, c4 = e & 3;
            float4 v = *reinterpret_cast<const float4*>(
                &A[(size_t)(row0+r)*K + k0 + c4*4]);
            As[c4*4+0][r] = v.x; As[c4*4+1][r] = v.y;
            As[c4*4+2][r] = v.z; As[c4*4+3][r] = v.w;
        }
        for (int e = tid; e < 256; e += 128) {
            int r = e >> 4, c4 = e & 15;
            *reinterpret_cast<float4*>(&Bs[r][c4*4]) =
                *reinterpret_cast<const float4*>(
                    &B[(size_t)(k0+r)*N + col0 + c4*4]);
        }
        __syncthreads();
#pragma unroll
        for (int kk = 0; kk < 16; kk++) {
            float a[8];
#pragma unroll
            for (int m = 0; m < 8; m++) a[m] = As[kk][ty*8 + m];
            float4 b = *reinterpret_cast<const float4*>(&Bs[kk][tx*4]);
#pragma unroll
            for (int m = 0; m < 8; m++) {
                acc[m][0] += a[m]*b.x; acc[m][1] += a[m]*b.y;
                acc[m][2] += a[m]*b.z; acc[m][3] += a[m]*b.w;
            }
        }
        __syncthreads();
    }
    float* Cz = C + (size_t)blockIdx.z * M * N;
#pragma unroll
    for (int m = 0; m < 8; m++) {
        int r = row0 + ty*8 + m;
        float4 v = make_float4(acc[m][0], acc[m][1], acc[m][2], acc[m][3]);
        *reinterpret_cast<float4*>(&Cz[(size_t)r*N + col0 + tx*4]) = v;
    }
}

// ------------- split-K reduce (+ output bias) -------------
__global__ __launch_bounds__(256) void reduce_k(
    float* __restrict__ out, const float* __restrict__ bout)
{
    int e = blockIdx.x * 256 + threadIdx.x;
    if (e >= NT * DIM) return;
    float s = 0.f;
#pragma unroll
    for (int z = 0; z < SPLITK; z++) s += g_part[(size_t)z*NT*DIM + e];
    out[e] = s + bout[e % DIM];
}

// ------------- relayout + rotate points to global frame -------------
__global__ __launch_bounds__(128) void relayout(
    const float* __restrict__ rot, const float* __restrict__ trans)
{
    const int i = blockIdx.x, t = threadIdx.x;
    __shared__ float R[9], tv[3];
    if (t < 9) R[t]  = rot[i*9 + t];
    if (t < 3) tv[t] = trans[i*3 + t];
    __syncthreads();
    const float* pr = g_proj + (size_t)i * NPROJ;
    for (int e = t; e < NH*16; e += 128) {
        int h = e/16, d = e%16;
        g_qs[((size_t)h*NT+i)*16+d] = pr[      h*16+d];
        g_ks[((size_t)h*NT+i)*16+d] = pr[192 + h*16+d];
        g_vs[((size_t)h*NT+i)*16+d] = pr[384 + h*16+d];
    }
    for (int e = t; e < NH*4; e += 128) {
        int h = e/4, p = e%4;
        const float* s = pr + 576 + h*12 + p*3;
        float x=s[0], y=s[1], z=s[2];
        float* o = g_qpg + ((size_t)h*NT+i)*12 + p*3;
        o[0]=R[0]*x+R[1]*y+R[2]*z+tv[0];
        o[1]=R[3]*x+R[4]*y+R[5]*z+tv[1];
        o[2]=R[6]*x+R[7]*y+R[8]*z+tv[2];
        s = pr + 720 + h*12 + p*3; x=s[0]; y=s[1]; z=s[2];
        o = g_kpg + ((size_t)h*NT+i)*12 + p*3;
        o[0]=R[0]*x+R[1]*y+R[2]*z+tv[0];
        o[1]=R[3]*x+R[4]*y+R[5]*z+tv[1];
        o[2]=R[6]*x+R[7]*y+R[8]*z+tv[2];
    }
    for (int e = t; e < NH*8; e += 128) {
        int h = e/8, p = e%8;
        const float* s = pr + 864 + h*24 + p*3;
        float x=s[0], y=s[1], z=s[2];
        float* o = g_vpg + ((size_t)h*NT+i)*24 + p*3;
        o[0]=R[0]*x+R[1]*y+R[2]*z+tv[0];
        o[1]=R[3]*x+R[4]*y+R[5]*z+tv[1];
        o[2]=R[6]*x+R[7]*y+R[8]*z+tv[2];
    }
}

// ------------- fused attention + pair-bias GEMM (latency-tuned) -------------
#define PRS_OFF 0                    // [3][32][132]
#define ACC_OFF 12672                // [3][12][168]
#define PPS_OFF 18720                // [3][12] rows, stride 33
#define QSS_OFF 19908
#define QPS_OFF 20484
#define MST_OFF 20916
#define LST_OFF 20952
#define FAC_OFF 20988
#define RS_OFF  21024
#define TV_OFF  21051
#define WT_OFF  21060                // [12][132] transposed Wpb
#define BB_OFF  22644                // [12]
#define BT_OFF  22656                // [3][12] rows, stride 33
#define SMEM_FLOATS 23844

__global__ __launch_bounds__(384, 2) void attn_k(
    const float* __restrict__ pair, const float* __restrict__ rot,
    const float* __restrict__ trans, const float* __restrict__ pwts,
    const float* __restrict__ Wpb, const float* __restrict__ bpb)
{
    extern __shared__ float sm[];
    float* prs  = sm + PRS_OFF;
    float* accs = sm + ACC_OFF;
    float* pps  = sm + PPS_OFF;
    float* qss  = sm + QSS_OFF;
    float* qps  = sm + QPS_OFF;
    float* mst  = sm + MST_OFF;
    float* lst  = sm + LST_OFF;
    float* facs = sm + FAC_OFF;
    float* Rs   = sm + RS_OFF;
    float* tvs  = sm + TV_OFF;
    float* wTs  = sm + WT_OFF;
    float* bbs  = sm + BB_OFF;
    float* bts  = sm + BT_OFF;

    const int i0 = blockIdx.x * TI;
    const int t  = threadIdx.x;
    const int h  = t >> 5, lane = t & 31;

    // pair-accumulate roles
    const int hg = t & 1;
    const int jq = (t >> 1) & 1;
    const int cc = (t >> 2) & 31;
    const int qq = t >> 7;
    // scalar/point roles: q-triples adjacent so V loads broadcast 3-way
    const bool has_sp = (t < 360);
    const int q2  = t % 3;
    const int u3  = t / 3;
    const int hh2 = u3 / 10;
    const int c2  = u3 % 10;
    const float* vbase;
    int vstride;
    if (c2 < 4) { vbase = g_vs  + (size_t)hh2*NT*16 + c2*4;     vstride = 16; }
    else        { vbase = g_vpg + (size_t)hh2*NT*24 + (c2-4)*4; vstride = 24; }
    // bias roles: 96 threads, thread = (rowgroup rg, head-triple bg)
    const int rg = t >> 2;
    const int bg = t & 3;

    float4 pacc[6];
#pragma unroll
    for (int m = 0; m < 6; m++) pacc[m] = make_float4(0.f,0.f,0.f,0.f);
    float4 spacc = make_float4(0.f,0.f,0.f,0.f);

    for (int e = t; e < TI*NH*16;  e += 384) {
        int q = e / (NH*16), rem = e % (NH*16);
        qss[e] = g_qs[((size_t)(rem/16)*NT + i0 + q)*16 + rem%16];
    }
    for (int e = t; e < TI*NH*12;  e += 384) {
        int q = e / (NH*12), rem = e % (NH*12);
        qps[e] = g_qpg[((size_t)(rem/12)*NT + i0 + q)*12 + rem%12];
    }
    for (int e = t; e < NH*PD; e += 384)
        wTs[(e >> 7)*132 + (e & 127)] = Wpb[(e & 127)*12 + (e >> 7)];
    if (t < NH) bbs[t] = bpb[t];
    if (t < TI*NH) { mst[t] = -1e30f; lst[t] = 0.f; }
    if (t < TI*9)  Rs[t]  = rot[(i0 + t/9)*9 + t%9];
    if (t < TI*3)  tvs[t] = trans[(i0 + t/3)*3 + t%3];
    __syncthreads();

    float wv = pwts[h];
    float pwh = (wv > 20.f) ? wv : log1pf(expf(wv));
    const float pscale = -0.5f * POINT_SCALE * pwh;

    for (int jt = 0; jt < NTILE; jt++) {
        const int j0 = jt * 32;
        // ---- stage pair tiles (unrolled: 8 LDGs in flight) ----
#pragma unroll
        for (int u = 0; u < 8; u++) {
            int e = t + u*384;
            int q = e >> 10, rem = e & 1023;
            int r = rem >> 5, c = rem & 31;
            float4 v = *reinterpret_cast<const float4*>(
                pair + ((size_t)(i0+q)*NT + j0 + r)*PD + c*4);
            *reinterpret_cast<float4*>(&prs[(q*32 + r)*132 + c*4]) = v;
        }
        __syncthreads();
        // ---- K loads issued BEFORE bias barrier: latency hides under bias ----
        const int j = j0 + lane;
        const float4* krp = reinterpret_cast<const float4*>(g_ks  + ((size_t)h*NT + j)*16);
        const float4* kpp = reinterpret_cast<const float4*>(g_kpg + ((size_t)h*NT + j)*12);
        float4 k0 = krp[0], k1 = krp[1], k2 = krp[2], k3 = krp[3];
        float4 p0 = kpp[0], p1 = kpp[1], p2 = kpp[2];
        // ---- fused pair-bias: 96 threads x (4 strided rows x 3 heads) ----
        if (t < 96) {
            const float* w0 = wTs + (3*bg+0)*132;
            const float* w1 = wTs + (3*bg+1)*132;
            const float* w2 = wTs + (3*bg+2)*132;
            float b[4][3];
#pragma unroll
            for (int r = 0; r < 4; r++)
#pragma unroll
                for (int k = 0; k < 3; k++) b[r][k] = 0.f;
#pragma unroll 4
            for (int k4 = 0; k4 < 32; k4++) {
                float4 wa = *reinterpret_cast<const float4*>(w0 + k4*4);
                float4 wb = *reinterpret_cast<const float4*>(w1 + k4*4);
                float4 wc = *reinterpret_cast<const float4*>(w2 + k4*4);
#pragma unroll
                for (int r = 0; r < 4; r++) {
                    float4 v = *reinterpret_cast<const float4*>(
                        &prs[(rg + 24*r)*132 + k4*4]);
                    b[r][0] += v.x*wa.x + v.y*wa.y + v.z*wa.z + v.w*wa.w;
                    b[r][1] += v.x*wb.x + v.y*wb.y + v.z*wb.z + v.w*wb.w;
                    b[r][2] += v.x*wc.x + v.y*wc.y + v.z*wc.z + v.w*wc.w;
                }
            }
#pragma unroll
            for (int r = 0; r < 4; r++) {
                int row = rg + 24*r;
                int bq = row >> 5, br = row & 31;
#pragma unroll
                for (int k = 0; k < 3; k++)
                    bts[(bq*NH + 3*bg+k)*33 + br] =
                        (b[r][k] + bbs[3*bg+k]) * PAIR_SCALE;
            }
        }
        __syncthreads();
        // ---- logits: interleaved 3-q softmax chains (no __syncwarp) ----
        {
            float s[TI];
#pragma unroll
            for (int q = 0; q < TI; q++) {
                const float4* qsv = reinterpret_cast<const float4*>(qss + (q*NH + h)*16);
                const float4* qpv = reinterpret_cast<const float4*>(qps + (q*NH + h)*12);
                float4 a0 = qsv[0], a1 = qsv[1], a2 = qsv[2], a3 = qsv[3];
                float sv = a0.x*k0.x + a0.y*k0.y + a0.z*k0.z + a0.w*k0.w
                         + a1.x*k1.x + a1.y*k1.y + a1.z*k1.z + a1.w*k1.w
                         + a2.x*k2.x + a2.y*k2.y + a2.z*k2.z + a2.w*k2.w
                         + a3.x*k3.x + a3.y*k3.y + a3.z*k3.z + a3.w*k3.w;
                sv *= SCALAR_SCALE;
                float4 b0 = qpv[0], b1 = qpv[1], b2 = qpv[2];
                float dx, dist = 0.f;
                dx = b0.x-p0.x; dist += dx*dx; dx = b0.y-p0.y; dist += dx*dx;
                dx = b0.z-p0.z; dist += dx*dx; dx = b0.w-p0.w; dist += dx*dx;
                dx = b1.x-p1.x; dist += dx*dx; dx = b1.y-p1.y; dist += dx*dx;
                dx = b1.z-p1.z; dist += dx*dx; dx = b1.w-p1.w; dist += dx*dx;
                dx = b2.x-p2.x; dist += dx*dx; dx = b2.y-p2.y; dist += dx*dx;
                dx = b2.z-p2.z; dist += dx*dx; dx = b2.w-p2.w; dist += dx*dx;
                sv += pscale * dist;
                sv += bts[(q*NH + h)*33 + lane];
                s[q] = sv;
            }
            float mx[TI];
#pragma unroll
            for (int q = 0; q < TI; q++) mx[q] = s[q];
#pragma unroll
            for (int o = 16; o; o >>= 1) {
#pragma unroll
                for (int q = 0; q < TI; q++)
                    mx[q] = fmaxf(mx[q], __shfl_xor_sync(~0u, mx[q], o));
            }
            float mold[TI], mnew[TI], ps[TI];
#pragma unroll
            for (int q = 0; q < TI; q++) {
                mold[q] = mst[q*NH + h];
                mnew[q] = fmaxf(mold[q], mx[q]);
                float p = __expf(s[q] - mnew[q]);
                pps[(q*NH + h)*33 + lane] = p;
                ps[q] = p;
            }
#pragma unroll
            for (int o = 16; o; o >>= 1) {
#pragma unroll
                for (int q = 0; q < TI; q++)
                    ps[q] += __shfl_xor_sync(~0u, ps[q], o);
            }
            if (lane == 0) {
#pragma unroll
                for (int q = 0; q < TI; q++) {
                    float f = __expf(mold[q] - mnew[q]);
                    facs[q*NH + h] = f;
                    lst[q*NH + h] = lst[q*NH + h]*f + ps[q];
                    mst[q*NH + h] = mnew[q];
                }
            }
        }
        __syncthreads();
        // ---- pair accumulate in registers ----
        {
            const float* fq = facs + qq*NH + hg*6;
            float f0=fq[0], f1=fq[1], f2=fq[2], f3=fq[3], f4=fq[4], f5=fq[5];
            pacc[0].x*=f0; pacc[0].y*=f0; pacc[0].z*=f0; pacc[0].w*=f0;
            pacc[1].x*=f1; pacc[1].y*=f1; pacc[1].z*=f1; pacc[1].w*=f1;
            pacc[2].x*=f2; pacc[2].y*=f2; pacc[2].z*=f2; pacc[2].w*=f2;
            pacc[3].x*=f3; pacc[3].y*=f3; pacc[3].z*=f3; pacc[3].w*=f3;
            pacc[4].x*=f4; pacc[4].y*=f4; pacc[4].z*=f4; pacc[4].w*=f4;
            pacc[5].x*=f5; pacc[5].y*=f5; pacc[5].z*=f5; pacc[5].w*=f5;
            const float* pbase = pps + (qq*NH + hg*6)*33 + jq*16;
            const float* prow  = prs + (qq*32 + jq*16)*132 + cc*4;
#pragma unroll
            for (int jj = 0; jj < 16; jj++) {
                float4 v = *reinterpret_cast<const float4*>(prow + jj*132);
                float pa = pbase[0*33+jj], pb = pbase[1*33+jj], pc = pbase[2*33+jj];
                float pd = pbase[3*33+jj], pe = pbase[4*33+jj], pf = pbase[5*33+jj];
                pacc[0].x += pa*v.x; pacc[0].y += pa*v.y; pacc[0].z += pa*v.z; pacc[0].w += pa*v.w;
                pacc[1].x += pb*v.x; pacc[1].y += pb*v.y; pacc[1].z += pb*v.z; pacc[1].w += pb*v.w;
                pacc[2].x += pc*v.x; pacc[2].y += pc*v.y; pacc[2].z += pc*v.z; pacc[2].w += pc*v.w;
                pacc[3].x += pd*v.x; pacc[3].y += pd*v.y; pacc[3].z += pd*v.z; pacc[3].w += pd*v.w;
                pacc[4].x += pe*v.x; pacc[4].y += pe*v.y; pacc[4].z += pe*v.z; pacc[4].w += pe*v.w;
                pacc[5].x += pf*v.x; pacc[5].y += pf*v.y; pacc[5].z += pf*v.z; pacc[5].w += pf*v.w;
            }
        }
        // ---- scalar/point accumulate ----
        if (has_sp) {
            float f = facs[q2*NH + hh2];
            spacc.x *= f; spacc.y *= f; spacc.z *= f; spacc.w *= f;
            const float* pph = pps + (q2*NH + hh2)*33;
            const float* src = vbase + (size_t)j0*vstride;
#pragma unroll 8
            for (int jv = 0; jv < 32; jv++) {
                float p = pph[jv];
                float4 v = *reinterpret_cast<const float4*>(src + (size_t)jv*vstride);
                spacc.x += p*v.x; spacc.y += p*v.y; spacc.z += p*v.z; spacc.w += p*v.w;
            }
        }
        __syncthreads();
    }

    // ---- merge register accumulators ----
    {
        int base = (qq*NH + hg*6)*168 + 40 + cc*4;
        if (jq == 0) {
#pragma unroll
            for (int m = 0; m < 6; m++)
                *reinterpret_cast<float4*>(accs + base + m*168) = pacc[m];
        }
        if (has_sp) {
            int off = (c2 < 4) ? c2*4 : 16 + (c2-4)*4;
            *reinterpret_cast<float4*>(accs + (q2*NH + hh2)*168 + off) = spacc;
        }
        __syncthreads();
        if (jq == 1) {
#pragma unroll
            for (int m = 0; m < 6; m++) {
                float4* p = reinterpret_cast<float4*>(accs + base + m*168);
                float4 a = *p;
                a.x += pacc[m].x; a.y += pacc[m].y; a.z += pacc[m].z; a.w += pacc[m].w;
                *p = a;
            }
        }
        __syncthreads();
    }

    // ---- finalize ----
    for (int e = t; e < TI*NH*16; e += 384) {
        int q = e / (NH*16), rem = e % (NH*16);
        int hh = rem/16, d = rem%16;
        g_feats[(size_t)(i0+q)*FEAT + hh*16 + d] =
            accs[(q*NH+hh)*168 + d] / lst[q*NH+hh];
    }
    for (int e = t; e < TI*NH*8; e += 384) {
        int q = e / (NH*8), rem = e % (NH*8);
        int hh = rem/8, p = rem%8;
        float inv = 1.f / lst[q*NH+hh];
        const float* R = Rs + q*9;
        const float* tv = tvs + q*3;
        const float* ac = accs + (q*NH+hh)*168 + 16 + p*3;
        float gx = ac[0]*inv - tv[0];
        float gy = ac[1]*inv - tv[1];
        float gz = ac[2]*inv - tv[2];
        float lx = R[0]*gx + R[3]*gy + R[6]*gz;
        float ly = R[1]*gx + R[4]*gy + R[7]*gz;
        float lz = R[2]*gx + R[5]*gy + R[8]*gz;
        float* fo = g_feats + (size_t)(i0+q)*FEAT;
        fo[192 + hh*24 + p*3 + 0] = lx;
        fo[192 + hh*24 + p*3 + 1] = ly;
        fo[192 + hh*24 + p*3 + 2] = lz;
        fo[480 + hh*8 + p] = sqrtf(lx*lx + ly*ly + lz*lz + 1e-8f);
    }
    for (int e = t; e < TI*NH*PD; e += 384) {
        int q = e / (NH*PD), rem = e % (NH*PD);
        int hh = rem/PD, d = rem%PD;
        g_feats[(size_t)(i0+q)*FEAT + 576 + hh*PD + d] =
            accs[(q*NH+hh)*168 + 40 + d] / lst[q*NH+hh];
    }
}

// ------------- launch -------------
extern "C" void kernel_launch(void* const* d_in, const int* in_sizes, int n_in,
                              void* d_out, int out_size)
{
    (void)in_sizes; (void)n_in; (void)out_size;
    const float* x     = (const float*)d_in[0];
    const float* pair  = (const float*)d_in[1];
    const float* rot   = (const float*)d_in[2];
    const float* trans = (const float*)d_in[3];
    const float* Wq    = (const float*)d_in[4];
    const float* Wk    = (const float*)d_in[5];
    const float* Wv    = (const float*)d_in[6];
    const float* Wpq   = (const float*)d_in[7];
    const float* Wpk   = (const float*)d_in[8];
    const float* Wpv   = (const float*)d_in[9];
    const float* Wpb   = (const float*)d_in[10];
    const float* bpb   = (const float*)d_in[11];
    const float* pwts  = (const float*)d_in[12];
    const float* Wout  = (const float*)d_in[13];
    const float* bout  = (const float*)d_in[14];
    float* out = (float*)d_out;

    cudaFuncSetAttribute(attn_k, cudaFuncAttributeMaxDynamicSharedMemorySize,
                         SMEM_FLOATS * 4);

    void *p_wall, *p_proj, *p_feats, *p_part;
    cudaGetSymbolAddress(&p_wall,  g_wall);
    cudaGetSymbolAddress(&p_proj,  g_proj);
    cudaGetSymbolAddress(&p_feats, g_feats);
    cudaGetSymbolAddress(&p_part,  g_part);

    pack_w<<<(DIM*NPROJ + 255)/256, 256>>>(Wq, Wk, Wv, Wpq, Wpk, Wpv);
    {
        dim3 g(NPROJ/64, NT/64, 1);
        sgemm_sk<<<g, 128>>>(x, (const float*)p_wall, (float*)p_proj,
                             NT, NPROJ, DIM);
    }
    relayout<<<NT, 128>>>(rot, trans);
    attn_k<<<NT/TI, 384, SMEM_FLOATS*4>>>(pair, rot, trans, pwts, Wpb, bpb);
    {
        dim3 g(DIM/64, NT/64, SPLITK);
        sgemm_sk<<<g, 128>>>((const float*)p_feats, Wout, (float*)p_part,
                             NT, DIM, FEAT);
    }
    reduce_k<<<(NT*DIM + 255)/256, 256>>>(out, bout);
}